// round 1
// baseline (speedup 1.0000x reference)
#include <cuda_runtime.h>

// Problem constants
#define NB 32      // batch
#define NS 128     // NEW_SEQ
#define ND 768     // D
#define NH 12      // heads
#define HD 64      // head dim
#define NM (NB*NS) // 4096 rows

// Scratch (no cudaMalloc allowed)
__device__ float g_K[NB*NS*ND];
__device__ float g_V[NB*NS*ND];
__device__ float g_A[NB*NS*ND];

// ---------------------------------------------------------------------------
// C[M,N] = X[M,K] * W[N,K]^T + bias[N]   (M=4096, N=768, K=768)
// Classic 128x128 tile, BK=8, 256 threads, 8x8 per thread.
// ---------------------------------------------------------------------------
__device__ __forceinline__ void gemm_core(const float* __restrict__ X,
                                          const float* __restrict__ W,
                                          const float* __restrict__ bias,
                                          float* __restrict__ C)
{
    __shared__ float As[8][128];
    __shared__ float Bs[8][128];

    const int bm = blockIdx.y * 128;
    const int bn = blockIdx.x * 128;
    const int tid = threadIdx.x;

    const int lrow = tid >> 1;          // 0..127
    const int lcol = (tid & 1) * 4;     // 0 or 4

    const int tr = (tid >> 4) * 8;      // thread row base within tile
    const int tc = (tid & 15) * 8;      // thread col base within tile

    float acc[8][8];
#pragma unroll
    for (int i = 0; i < 8; i++)
#pragma unroll
        for (int j = 0; j < 8; j++) acc[i][j] = 0.f;

    const float* Xp = X + (size_t)(bm + lrow) * ND + lcol;
    const float* Wp = W + (size_t)(bn + lrow) * ND + lcol;

    for (int k0 = 0; k0 < ND; k0 += 8) {
        float4 av = *(const float4*)(Xp + k0);
        float4 bv = *(const float4*)(Wp + k0);
        As[lcol + 0][lrow] = av.x; As[lcol + 1][lrow] = av.y;
        As[lcol + 2][lrow] = av.z; As[lcol + 3][lrow] = av.w;
        Bs[lcol + 0][lrow] = bv.x; Bs[lcol + 1][lrow] = bv.y;
        Bs[lcol + 2][lrow] = bv.z; Bs[lcol + 3][lrow] = bv.w;
        __syncthreads();
#pragma unroll
        for (int kk = 0; kk < 8; kk++) {
            float a[8], b[8];
            *(float4*)&a[0] = *(const float4*)&As[kk][tr];
            *(float4*)&a[4] = *(const float4*)&As[kk][tr + 4];
            *(float4*)&b[0] = *(const float4*)&Bs[kk][tc];
            *(float4*)&b[4] = *(const float4*)&Bs[kk][tc + 4];
#pragma unroll
            for (int i = 0; i < 8; i++)
#pragma unroll
                for (int j = 0; j < 8; j++)
                    acc[i][j] += a[i] * b[j];
        }
        __syncthreads();
    }

#pragma unroll
    for (int i = 0; i < 8; i++) {
        float* crow = C + (size_t)(bm + tr + i) * ND + bn + tc;
#pragma unroll
        for (int j = 0; j < 8; j += 4) {
            float4 o;
            o.x = acc[i][j + 0] + bias[bn + tc + j + 0];
            o.y = acc[i][j + 1] + bias[bn + tc + j + 1];
            o.z = acc[i][j + 2] + bias[bn + tc + j + 2];
            o.w = acc[i][j + 3] + bias[bn + tc + j + 3];
            *(float4*)(crow + j) = o;
        }
    }
}

// K and V projections fused via gridDim.z
__global__ __launch_bounds__(256, 2)
void sgemm_kv(const float* __restrict__ X,
              const float* __restrict__ Wk, const float* __restrict__ bk,
              const float* __restrict__ Wv, const float* __restrict__ bv)
{
    if (blockIdx.z == 0) gemm_core(X, Wk, bk, g_K);
    else                 gemm_core(X, Wv, bv, g_V);
}

// Output projection: reads g_A, writes d_out
__global__ __launch_bounds__(256, 2)
void sgemm_out(const float* __restrict__ Wo, const float* __restrict__ bo,
               float* __restrict__ C)
{
    gemm_core(g_A, Wo, bo, C);
}

// ---------------------------------------------------------------------------
// Attention, collapsed form. One block per (b, h), 128 threads.
//   l[j]   = dot(K[b,j,h], wk_a) + dot(desc[b,j-1,h], we_a)   (j>=1)
//   p[j]   = exp(l[j]-m),  Ssum = sum p,  Vsum[d] = sum p[j] V[b,j,h,d]
//   A[b,i,h,d] = (Vsum[d] - p[i] V[i,d]) / (Ssum - p[i])      (p[0]=0)
// ---------------------------------------------------------------------------
__global__ void attn_kernel(const float* __restrict__ desc,
                            const float* __restrict__ Wa)
{
    const int b = blockIdx.x / NH;
    const int h = blockIdx.x % NH;
    const int tid = threadIdx.x;   // 0..127

    __shared__ float p[NS];
    __shared__ float red[NS];
    __shared__ float vsum[HD];
    __shared__ float s_wk[HD], s_we[HD];
    __shared__ float s_S;

    if (tid < HD) {
        s_wk[tid] = Wa[HD + tid];        // wk_a = Wa[0, 64:128]
        s_we[tid] = Wa[2 * HD + tid];    // we_a = Wa[0, 128:192]
    }
    __syncthreads();

    const float* Kp = g_K + (size_t)b * NS * ND + h * HD;
    const float* Vp = g_V + (size_t)b * NS * ND + h * HD;

    // logit for position j = tid (j=0 excluded: column 0 always masked)
    float l = -1e30f;
    if (tid >= 1) {
        const float* kr = Kp + (size_t)tid * ND;
        const float* er = desc + ((size_t)b * (NS - 1) + (tid - 1)) * ND + h * HD;
        float acc = 0.f;
#pragma unroll 8
        for (int d = 0; d < HD; d++)
            acc += kr[d] * s_wk[d] + er[d] * s_we[d];
        l = acc;
    }

    // block max reduce
    red[tid] = l;
    __syncthreads();
    for (int off = 64; off > 0; off >>= 1) {
        if (tid < off) red[tid] = fmaxf(red[tid], red[tid + off]);
        __syncthreads();
    }
    const float m = red[0];
    __syncthreads();

    const float pe = (tid >= 1) ? expf(l - m) : 0.f;
    p[tid] = pe;
    red[tid] = pe;
    __syncthreads();
    for (int off = 64; off > 0; off >>= 1) {
        if (tid < off) red[tid] += red[tid + off];
        __syncthreads();
    }
    if (tid == 0) s_S = red[0];
    __syncthreads();

    // Vsum[d] = sum_j p[j] * V[j,d] ; tid -> (d = tid&63, half = tid>>6)
    const int d = tid & 63;
    const int half = tid >> 6;
    {
        float acc = 0.f;
        for (int j = 1 + half; j < NS; j += 2)
            acc += p[j] * Vp[(size_t)j * ND + d];
        red[tid] = acc;
        __syncthreads();
        if (tid < HD) vsum[tid] = red[tid] + red[tid + HD];
        __syncthreads();
    }

    const float Sall = s_S;
    const float vs = vsum[d];
    float* Ap = g_A + (size_t)b * NS * ND + h * HD + d;
    for (int i = half; i < NS; i += 2) {
        const float pi = p[i];
        const float o = (vs - pi * Vp[(size_t)i * ND + d]) / (Sall - pi);
        Ap[(size_t)i * ND] = o;
    }
}

// ---------------------------------------------------------------------------
extern "C" void kernel_launch(void* const* d_in, const int* in_sizes, int n_in,
                              void* d_out, int out_size)
{
    const float* desc = (const float*)d_in[0];
    const float* nv   = (const float*)d_in[1];
    // d_in[2]=Wq, d_in[3]=bq — dead (score_q cancels in softmax)
    const float* Wk   = (const float*)d_in[4];
    const float* bk   = (const float*)d_in[5];
    const float* Wv   = (const float*)d_in[6];
    const float* bv   = (const float*)d_in[7];
    const float* Wo   = (const float*)d_in[8];
    const float* bo   = (const float*)d_in[9];
    const float* Wa   = (const float*)d_in[10];
    // d_in[11]=ba — dead (cancels in softmax)
    float* out = (float*)d_out;

    dim3 grid_kv(ND / 128, NM / 128, 2);   // 6 x 32 x 2
    dim3 grid_o (ND / 128, NM / 128, 1);   // 6 x 32

    sgemm_kv<<<grid_kv, 256>>>(nv, Wk, bk, Wv, bv);
    attn_kernel<<<NB * NH, 128>>>(desc, Wa);
    sgemm_out<<<grid_o, 256>>>(Wo, bo, out);
}

// round 3
// speedup vs baseline: 3.1186x; 3.1186x over previous
#include <cuda_runtime.h>
#include <cuda_bf16.h>
#include <cstdint>

// Problem constants
#define NB 32      // batch
#define NS 128     // NEW_SEQ
#define ND 768     // D
#define NH 12      // heads
#define HD 64      // head dim
#define NM (NB*NS) // 4096 rows

// Scratch
__device__ float g_V[NB*NS*ND];
__device__ float g_A[NB*NS*ND];
__device__ float g_U[NH*ND];       // u_h[k] = sum_d wk_a[d] * Wk[h*64+d, k]
__device__ float g_c[NH];          // c_h = wk_a . bk[h*64:]
__device__ float g_sk[NB*NH*NS];   // score_k + c per (b,h,j)

// ---------------------------------------------------------------------------
// helpers
// ---------------------------------------------------------------------------
__device__ __forceinline__ uint32_t smem_u32(const void* p) {
    uint32_t a;
    asm("{ .reg .u64 t; cvta.to.shared.u64 t, %1; cvt.u32.u64 %0, t; }"
        : "=r"(a) : "l"(p));
    return a;
}
#define SWZ(o) ((o) ^ (((o) >> 3) & 0x70))

__device__ __forceinline__ void ldm_x4(uint32_t* r, uint32_t addr) {
    asm volatile("ldmatrix.sync.aligned.m8n8.x4.shared.b16 {%0,%1,%2,%3}, [%4];"
                 : "=r"(r[0]), "=r"(r[1]), "=r"(r[2]), "=r"(r[3]) : "r"(addr));
}
__device__ __forceinline__ void mma_bf16(float* d, const uint32_t* a, const uint32_t* b) {
    asm volatile(
        "mma.sync.aligned.m16n8k16.row.col.f32.bf16.bf16.f32 "
        "{%0,%1,%2,%3}, {%4,%5,%6,%7}, {%8,%9}, {%0,%1,%2,%3};"
        : "+f"(d[0]), "+f"(d[1]), "+f"(d[2]), "+f"(d[3])
        : "r"(a[0]), "r"(a[1]), "r"(a[2]), "r"(a[3]), "r"(b[0]), "r"(b[1]));
}
__device__ __forceinline__ uint32_t pack2bf(float a, float b) {
    __nv_bfloat162 t = __floats2bfloat162_rn(a, b);
    return *(uint32_t*)&t;
}
__device__ __forceinline__ float bf_hi(float x) {
    return __bfloat162float(__float2bfloat16(x));
}

// ---------------------------------------------------------------------------
// mma.sync GEMM: C[4096,768] = X[4096,768] * W[768,768]^T + bias
// CTA tile 128x128, BK=64, 512 threads (warp grid 4x4, 32x32 per warp).
// Split-bf16 3-pass for fp32-class accuracy. Smem layout per K-chunk:
//   A_hi @0, A_lo @16384, B_hi @32768, B_lo @49152 (each 128x64 bf16, SW128).
// ---------------------------------------------------------------------------
__global__ __launch_bounds__(512, 1)
void gemm_mma(const float* __restrict__ X, const float* __restrict__ W,
              const float* __restrict__ bias, float* __restrict__ C)
{
    extern __shared__ __align__(1024) char sm[];
    const int tid = threadIdx.x;
    const int lane = tid & 31, w = tid >> 5;
    const int wm = w >> 2, wn = w & 3;
    const int bm = blockIdx.y * 128, bn = blockIdx.x * 128;
    const uint32_t smb = smem_u32(sm);

    const float* Xb = X + (size_t)bm * ND;
    const float* Wb = W + (size_t)bn * ND;

    // fragment address components (byte offsets, pre-swizzle)
    const uint32_t a_row = (uint32_t)(wm * 32 + (lane & 15));
    const uint32_t a_kh  = (uint32_t)((lane >> 4) << 4);           // k-half *16B
    const uint32_t b_row = (uint32_t)(wn * 32 + (lane & 7) + ((lane >> 4) << 3));
    const uint32_t b_kh  = (uint32_t)(((lane >> 3) & 1) << 4);

    float acc[2][4][4];
#pragma unroll
    for (int mt = 0; mt < 2; mt++)
#pragma unroll
        for (int nt = 0; nt < 4; nt++)
#pragma unroll
            for (int i = 0; i < 4; i++) acc[mt][nt][i] = 0.f;

    float4 pa[4], pb[4];

    auto LOAD = [&](int c) {
#pragma unroll
        for (int i = 0; i < 4; i++) {
            const int lin = tid + i * 512;
            const int r = lin >> 4, col = (lin & 15) << 2;
            pa[i] = *(const float4*)(Xb + (size_t)r * ND + c * 64 + col);
            pb[i] = *(const float4*)(Wb + (size_t)r * ND + c * 64 + col);
        }
    };
    auto STORE = [&]() {
#pragma unroll
        for (int i = 0; i < 4; i++) {
            const int lin = tid + i * 512;
            const int r = lin >> 4, colb = (lin & 15) << 3;
            const uint32_t so = SWZ((uint32_t)(r * 128 + colb));
            float4 va = pa[i];
            float h0 = bf_hi(va.x), h1 = bf_hi(va.y), h2 = bf_hi(va.z), h3 = bf_hi(va.w);
            *(uint2*)(sm + 0 + so) =
                make_uint2(pack2bf(va.x, va.y), pack2bf(va.z, va.w));
            *(uint2*)(sm + 16384 + so) =
                make_uint2(pack2bf(va.x - h0, va.y - h1), pack2bf(va.z - h2, va.w - h3));
            float4 vb = pb[i];
            float g0 = bf_hi(vb.x), g1 = bf_hi(vb.y), g2 = bf_hi(vb.z), g3 = bf_hi(vb.w);
            *(uint2*)(sm + 32768 + so) =
                make_uint2(pack2bf(vb.x, vb.y), pack2bf(vb.z, vb.w));
            *(uint2*)(sm + 49152 + so) =
                make_uint2(pack2bf(vb.x - g0, vb.y - g1), pack2bf(vb.z - g2, vb.w - g3));
        }
    };

    LOAD(0);
    for (int c = 0; c < 12; c++) {
        STORE();
        __syncthreads();
        if (c < 11) LOAD(c + 1);   // LDGs in flight while MMAs run

#pragma unroll
        for (int ks = 0; ks < 4; ks++) {
            uint32_t ah[2][4], al[2][4], bh[2][4], bl[2][4];
#pragma unroll
            for (int mt = 0; mt < 2; mt++) {
                const uint32_t byo = (a_row + mt * 16) * 128 + ks * 32 + a_kh;
                ldm_x4(ah[mt], smb + 0     + SWZ(byo));
                ldm_x4(al[mt], smb + 16384 + SWZ(byo));
            }
#pragma unroll
            for (int nt2 = 0; nt2 < 2; nt2++) {
                const uint32_t byo = (b_row + nt2 * 16) * 128 + ks * 32 + b_kh;
                ldm_x4(bh[nt2], smb + 32768 + SWZ(byo));
                ldm_x4(bl[nt2], smb + 49152 + SWZ(byo));
            }
#pragma unroll
            for (int mt = 0; mt < 2; mt++)
#pragma unroll
                for (int nt = 0; nt < 4; nt++) {
                    const uint32_t* bhp = &bh[nt >> 1][(nt & 1) * 2];
                    const uint32_t* blp = &bl[nt >> 1][(nt & 1) * 2];
                    mma_bf16(acc[mt][nt], ah[mt], bhp);
                    mma_bf16(acc[mt][nt], ah[mt], blp);
                    mma_bf16(acc[mt][nt], al[mt], bhp);
                }
        }
        __syncthreads();
    }

    // epilogue
    const int erow = bm + wm * 32 + (lane >> 2);
    const int ecol0 = bn + wn * 32 + ((lane & 3) << 1);
#pragma unroll
    for (int mt = 0; mt < 2; mt++)
#pragma unroll
        for (int nt = 0; nt < 4; nt++) {
            const int col = ecol0 + nt * 8;
            const float b0 = bias[col], b1 = bias[col + 1];
            const int r0 = erow + mt * 16;
            float2 o0 = make_float2(acc[mt][nt][0] + b0, acc[mt][nt][1] + b1);
            float2 o1 = make_float2(acc[mt][nt][2] + b0, acc[mt][nt][3] + b1);
            *(float2*)(C + (size_t)r0 * ND + col) = o0;
            *(float2*)(C + (size_t)(r0 + 8) * ND + col) = o1;
        }
}

// ---------------------------------------------------------------------------
// prep: g_U[h][k] = sum_d wk_a[d]*Wk[h*64+d][k];  g_c[h] = wk_a . bk[h*64:]
// ---------------------------------------------------------------------------
__global__ void prep_kernel(const float* __restrict__ Wk,
                            const float* __restrict__ bk,
                            const float* __restrict__ Wa)
{
    const int h = blockIdx.x;
    const int tid = threadIdx.x;
    __shared__ float swk[HD];
    if (tid < HD) swk[tid] = Wa[HD + tid];
    __syncthreads();
    for (int k = tid; k < ND; k += 256) {
        float a = 0.f;
#pragma unroll 8
        for (int d = 0; d < HD; d++)
            a += swk[d] * Wk[(size_t)(h * HD + d) * ND + k];
        g_U[h * ND + k] = a;
    }
    if (tid == 0) {
        float cc = 0.f;
        for (int d = 0; d < HD; d++) cc += swk[d] * bk[h * HD + d];
        g_c[h] = cc;
    }
}

// ---------------------------------------------------------------------------
// score: g_sk[b][h][j] = nv[b,j,:] . g_U[h] + g_c[h]
// ---------------------------------------------------------------------------
__global__ __launch_bounds__(384)
void score_kernel(const float* __restrict__ nv)
{
    __shared__ float s_nv[8][ND];
    const int b = blockIdx.x;
    const int j0 = blockIdx.y * 8;
    const int tid = threadIdx.x;
    const int w = tid >> 5, lane = tid & 31;

    const float* src = nv + ((size_t)b * NS + j0) * ND;
#pragma unroll
    for (int it = 0; it < 4; it++) {
        int lin = tid + it * 384;
        *(float4*)(&s_nv[0][0] + lin * 4) = *(const float4*)(src + lin * 4);
    }
    __syncthreads();

    float u[24];
#pragma unroll
    for (int t = 0; t < 24; t++) u[t] = g_U[w * ND + t * 32 + lane];
    const float ch = g_c[w];

    for (int j = 0; j < 8; j++) {
        float acc = 0.f;
#pragma unroll
        for (int t = 0; t < 24; t++) acc += s_nv[j][t * 32 + lane] * u[t];
#pragma unroll
        for (int off = 16; off > 0; off >>= 1)
            acc += __shfl_xor_sync(0xFFFFFFFF, acc, off);
        if (lane == 0) g_sk[((size_t)b * NH + w) * NS + j0 + j] = acc + ch;
    }
}

// ---------------------------------------------------------------------------
// attention (collapsed softmax): block per (b,h), 256 threads
// ---------------------------------------------------------------------------
__global__ __launch_bounds__(256)
void attn_kernel(const float* __restrict__ desc,
                 const float* __restrict__ Wa)
{
    const int b = blockIdx.x / NH;
    const int h = blockIdx.x % NH;
    const int tid = threadIdx.x;

    __shared__ float p[NS];
    __shared__ float red[256];
    __shared__ float vsum[HD];
    __shared__ float s_we[HD];
    __shared__ float s_S;

    if (tid < HD) s_we[tid] = Wa[2 * HD + tid];
    __syncthreads();

    const float* Vp = g_V + (size_t)b * NS * ND + h * HD;

    float l = -1e30f;
    if (tid >= 1 && tid < NS) {
        const float* er = desc + ((size_t)b * (NS - 1) + (tid - 1)) * ND + h * HD;
        float acc = 0.f;
#pragma unroll 8
        for (int d = 0; d < HD; d++) acc += er[d] * s_we[d];
        l = acc + g_sk[((size_t)b * NH + h) * NS + tid];
    }

    red[tid] = l;
    __syncthreads();
    for (int off = 128; off > 0; off >>= 1) {
        if (tid < off) red[tid] = fmaxf(red[tid], red[tid + off]);
        __syncthreads();
    }
    const float m = red[0];
    __syncthreads();

    const float pe = (tid >= 1 && tid < NS) ? expf(l - m) : 0.f;
    if (tid < NS) p[tid] = pe;
    red[tid] = pe;
    __syncthreads();
    for (int off = 128; off > 0; off >>= 1) {
        if (tid < off) red[tid] += red[tid + off];
        __syncthreads();
    }
    if (tid == 0) s_S = red[0];
    __syncthreads();

    const int d = tid & 63;
    const int q = tid >> 6;
    {
        float acc = 0.f;
        for (int j = 1 + q; j < NS; j += 4)
            acc += p[j] * Vp[(size_t)j * ND + d];
        red[tid] = acc;
        __syncthreads();
        if (tid < HD)
            vsum[tid] = red[tid] + red[tid + 64] + red[tid + 128] + red[tid + 192];
        __syncthreads();
    }

    const float Sall = s_S;
    const float vs = vsum[d];
    float* Ap = g_A + (size_t)b * NS * ND + h * HD + d;
    for (int i = q; i < NS; i += 4) {
        const float pi = p[i];
        Ap[(size_t)i * ND] = (vs - pi * Vp[(size_t)i * ND + d]) / (Sall - pi);
    }
}

// ---------------------------------------------------------------------------
extern "C" void kernel_launch(void* const* d_in, const int* in_sizes, int n_in,
                              void* d_out, int out_size)
{
    const float* desc = (const float*)d_in[0];
    const float* nv   = (const float*)d_in[1];
    // d_in[2]=Wq, d_in[3]=bq dead (cancel in softmax)
    const float* Wk   = (const float*)d_in[4];
    const float* bk   = (const float*)d_in[5];
    const float* Wv   = (const float*)d_in[6];
    const float* bv   = (const float*)d_in[7];
    const float* Wo   = (const float*)d_in[8];
    const float* bo   = (const float*)d_in[9];
    const float* Wa   = (const float*)d_in[10];
    // d_in[11]=ba dead
    float* out = (float*)d_out;

    cudaFuncSetAttribute(gemm_mma, cudaFuncAttributeMaxDynamicSharedMemorySize, 65536);

    float* pV; cudaGetSymbolAddress((void**)&pV, g_V);
    float* pA; cudaGetSymbolAddress((void**)&pA, g_A);

    dim3 ggrid(ND / 128, NM / 128);            // 6 x 32 = 192 CTAs
    gemm_mma<<<ggrid, 512, 65536>>>(nv, Wv, bv, pV);
    prep_kernel<<<NH, 256>>>(Wk, bk, Wa);
    score_kernel<<<dim3(NB, 16), 384>>>(nv);
    attn_kernel<<<NB * NH, 256>>>(desc, Wa);
    gemm_mma<<<ggrid, 512, 65536>>>(pA, Wo, bo, out);
}

// round 4
// speedup vs baseline: 4.1148x; 1.3194x over previous
#include <cuda_runtime.h>
#include <cuda_bf16.h>
#include <cstdint>

#define NB 32
#define NS 128
#define ND 768
#define NH 12
#define HD 64
#define NM (NB*NS)   // 4096

// Scratch
__device__ float g_V[NB*NS*ND];                       // V projection (fp32)
__device__ __nv_bfloat16 g_nvh[NB*NS*ND];             // nv hi/lo bf16
__device__ __nv_bfloat16 g_nvl[NB*NS*ND];
__device__ __nv_bfloat16 g_Ah[NB*NS*ND];              // attn out hi/lo
__device__ __nv_bfloat16 g_Al[NB*NS*ND];
__device__ __nv_bfloat16 g_Wvh[ND*ND], g_Wvl[ND*ND];
__device__ __nv_bfloat16 g_Woh[ND*ND], g_Wol[ND*ND];
__device__ float g_U[NH*ND];
__device__ float g_c[NH];
__device__ float g_sk[NB*NH*NS];

// ---------------------------------------------------------------------------
__device__ __forceinline__ uint32_t smem_u32(const void* p) {
    uint32_t a;
    asm("{ .reg .u64 t; cvta.to.shared.u64 t, %1; cvt.u32.u64 %0, t; }"
        : "=r"(a) : "l"(p));
    return a;
}
#define SWZ(o) ((o) ^ (((o) >> 3) & 0x70))

__device__ __forceinline__ void ldm_x4(uint32_t* r, uint32_t addr) {
    asm volatile("ldmatrix.sync.aligned.m8n8.x4.shared.b16 {%0,%1,%2,%3}, [%4];"
                 : "=r"(r[0]), "=r"(r[1]), "=r"(r[2]), "=r"(r[3]) : "r"(addr));
}
__device__ __forceinline__ void mma_bf16(float* d, const uint32_t* a, const uint32_t* b) {
    asm volatile(
        "mma.sync.aligned.m16n8k16.row.col.f32.bf16.bf16.f32 "
        "{%0,%1,%2,%3}, {%4,%5,%6,%7}, {%8,%9}, {%0,%1,%2,%3};"
        : "+f"(d[0]), "+f"(d[1]), "+f"(d[2]), "+f"(d[3])
        : "r"(a[0]), "r"(a[1]), "r"(a[2]), "r"(a[3]), "r"(b[0]), "r"(b[1]));
}
__device__ __forceinline__ void cpa16(uint32_t dst, const void* src) {
    asm volatile("cp.async.cg.shared.global [%0], [%1], 16;"
                 :: "r"(dst), "l"(src) : "memory");
}
__device__ __forceinline__ void cpa_commit() {
    asm volatile("cp.async.commit_group;" ::: "memory");
}
__device__ __forceinline__ void cpa_wait0() {
    asm volatile("cp.async.wait_group 0;" ::: "memory");
}
__device__ __forceinline__ uint32_t pack2bf(float a, float b) {
    __nv_bfloat162 t = __floats2bfloat162_rn(a, b);
    return *(uint32_t*)&t;
}
__device__ __forceinline__ float bf_hi(float x) {
    return __bfloat162float(__float2bfloat16(x));
}

// ---------------------------------------------------------------------------
// GEMM: C[4096,768] = X * W^T + bias, X/W given as hi/lo bf16 split arrays.
// CTA tile 128(M)x64(N), BK=64, 256 thr (8 warps 32x32), cp.async double buf.
// Smem stage (48KB): A_hi@0  A_lo@16K  B_hi@32K  B_lo@40K, SW128 swizzle.
// 3-pass split MMA: ah*bh + ah*bl + al*bh.
// ---------------------------------------------------------------------------
#define STG 49152
__global__ __launch_bounds__(256, 2)
void gemm_cp(const __nv_bfloat16* __restrict__ Xh, const __nv_bfloat16* __restrict__ Xl,
             const __nv_bfloat16* __restrict__ Wh, const __nv_bfloat16* __restrict__ Wl,
             const float* __restrict__ bias, float* __restrict__ C)
{
    extern __shared__ __align__(1024) char sm[];
    const int tid = threadIdx.x;
    const int lane = tid & 31, w = tid >> 5;
    const int wm = w >> 1, wn = w & 1;
    const int bm = blockIdx.y * 128, bn = blockIdx.x * 64;
    const uint32_t smb = smem_u32(sm);

    const uint32_t a_row = (uint32_t)(wm * 32 + (lane & 15));
    const uint32_t a_kh  = (uint32_t)((lane >> 4) << 4);
    const uint32_t b_row = (uint32_t)(wn * 32 + (lane & 7) + ((lane >> 4) << 3));
    const uint32_t b_kh  = (uint32_t)(((lane >> 3) & 1) << 4);

    float acc[2][4][4];
#pragma unroll
    for (int mt = 0; mt < 2; mt++)
#pragma unroll
        for (int nt = 0; nt < 4; nt++)
#pragma unroll
            for (int i = 0; i < 4; i++) acc[mt][nt][i] = 0.f;

    auto ISSUE = [&](int c, int s) {
        const uint32_t sb = smb + s * STG;
        const int k0 = c * 64;
#pragma unroll
        for (int it = 0; it < 4; it++) {             // A: 128 rows x 8 k-blocks
            const int L = tid + it * 256;
            const int r = L >> 3, k8 = (L & 7);
            const uint32_t so = SWZ((uint32_t)(r * 128 + k8 * 16));
            const size_t go = (size_t)(bm + r) * ND + k0 + k8 * 8;
            cpa16(sb + so,         Xh + go);
            cpa16(sb + 16384 + so, Xl + go);
        }
#pragma unroll
        for (int it = 0; it < 2; it++) {             // B: 64 rows x 8 k-blocks
            const int L = tid + it * 256;
            const int r = L >> 3, k8 = (L & 7);
            const uint32_t so = SWZ((uint32_t)(r * 128 + k8 * 16));
            const size_t go = (size_t)(bn + r) * ND + k0 + k8 * 8;
            cpa16(sb + 32768 + so, Wh + go);
            cpa16(sb + 40960 + so, Wl + go);
        }
        cpa_commit();
    };

    ISSUE(0, 0);
    for (int c = 0; c < 12; c++) {
        cpa_wait0();
        __syncthreads();
        if (c < 11) ISSUE(c + 1, (c + 1) & 1);
        const uint32_t sb = smb + (c & 1) * STG;

#pragma unroll
        for (int ks = 0; ks < 4; ks++) {
            uint32_t ah[2][4], al[2][4], bh[2][4], bl[2][4];
#pragma unroll
            for (int mt = 0; mt < 2; mt++) {
                const uint32_t byo = (a_row + mt * 16) * 128 + ks * 32 + a_kh;
                ldm_x4(ah[mt], sb + SWZ(byo));
                ldm_x4(al[mt], sb + 16384 + SWZ(byo));
            }
#pragma unroll
            for (int nt2 = 0; nt2 < 2; nt2++) {
                const uint32_t byo = (b_row + nt2 * 16) * 128 + ks * 32 + b_kh;
                ldm_x4(bh[nt2], sb + 32768 + SWZ(byo));
                ldm_x4(bl[nt2], sb + 40960 + SWZ(byo));
            }
#pragma unroll
            for (int mt = 0; mt < 2; mt++)
#pragma unroll
                for (int nt = 0; nt < 4; nt++) {
                    const uint32_t* bhp = &bh[nt >> 1][(nt & 1) * 2];
                    const uint32_t* blp = &bl[nt >> 1][(nt & 1) * 2];
                    mma_bf16(acc[mt][nt], ah[mt], bhp);
                    mma_bf16(acc[mt][nt], ah[mt], blp);
                    mma_bf16(acc[mt][nt], al[mt], bhp);
                }
        }
        __syncthreads();
    }

    const int erow = bm + wm * 32 + (lane >> 2);
    const int ecol0 = bn + wn * 32 + ((lane & 3) << 1);
#pragma unroll
    for (int mt = 0; mt < 2; mt++)
#pragma unroll
        for (int nt = 0; nt < 4; nt++) {
            const int col = ecol0 + nt * 8;
            const float b0 = bias[col], b1 = bias[col + 1];
            const int r0 = erow + mt * 16;
            *(float2*)(C + (size_t)r0 * ND + col) =
                make_float2(acc[mt][nt][0] + b0, acc[mt][nt][1] + b1);
            *(float2*)(C + (size_t)(r0 + 8) * ND + col) =
                make_float2(acc[mt][nt][2] + b0, acc[mt][nt][3] + b1);
        }
}

// ---------------------------------------------------------------------------
// Weight split: Wv, Wo -> hi/lo bf16
// ---------------------------------------------------------------------------
__global__ void cvtw_kernel(const float* __restrict__ Wv, const float* __restrict__ Wo)
{
    const int lin = blockIdx.x * 256 + threadIdx.x;    // float4 index
    const float* src = blockIdx.y ? Wo : Wv;
    uint32_t* hi = (uint32_t*)(blockIdx.y ? g_Woh : g_Wvh);
    uint32_t* lo = (uint32_t*)(blockIdx.y ? g_Wol : g_Wvl);
    float4 v = *(const float4*)(src + (size_t)lin * 4);
    float h0 = bf_hi(v.x), h1 = bf_hi(v.y), h2 = bf_hi(v.z), h3 = bf_hi(v.w);
    *(uint2*)(hi + (size_t)lin * 2) = make_uint2(pack2bf(v.x, v.y), pack2bf(v.z, v.w));
    *(uint2*)(lo + (size_t)lin * 2) =
        make_uint2(pack2bf(v.x - h0, v.y - h1), pack2bf(v.z - h2, v.w - h3));
}

// ---------------------------------------------------------------------------
// prep: g_U[h][k] = sum_d wk_a[d]*Wk[h*64+d][k];  g_c[h] = wk_a . bk[h*64:]
// ---------------------------------------------------------------------------
__global__ void prep_kernel(const float* __restrict__ Wk,
                            const float* __restrict__ bk,
                            const float* __restrict__ Wa)
{
    const int h = blockIdx.x;
    const int tid = threadIdx.x;
    __shared__ float swk[HD];
    if (tid < HD) swk[tid] = Wa[HD + tid];
    __syncthreads();
    for (int k = tid; k < ND; k += 256) {
        float a = 0.f;
#pragma unroll 8
        for (int d = 0; d < HD; d++)
            a += swk[d] * Wk[(size_t)(h * HD + d) * ND + k];
        g_U[h * ND + k] = a;
    }
    if (tid == 0) {
        float cc = 0.f;
        for (int d = 0; d < HD; d++) cc += swk[d] * bk[h * HD + d];
        g_c[h] = cc;
    }
}

// ---------------------------------------------------------------------------
// score + nv hi/lo split: g_sk[b][h][j] = nv[b,j,:].g_U[h] + g_c[h]
// ---------------------------------------------------------------------------
__global__ __launch_bounds__(384)
void score_cvt_kernel(const float* __restrict__ nv)
{
    __shared__ float s_nv[8][ND];
    const int b = blockIdx.x;
    const int j0 = blockIdx.y * 8;
    const int tid = threadIdx.x;
    const int w = tid >> 5, lane = tid & 31;

    const size_t gbase = ((size_t)b * NS + j0) * ND;       // element offset
    const float* src = nv + gbase;
    uint32_t* nvh = (uint32_t*)g_nvh;
    uint32_t* nvl = (uint32_t*)g_nvl;
#pragma unroll
    for (int it = 0; it < 4; it++) {
        int lin = tid + it * 384;                          // float4 idx in tile
        float4 v = *(const float4*)(src + lin * 4);
        *(float4*)(&s_nv[0][0] + lin * 4) = v;
        float h0 = bf_hi(v.x), h1 = bf_hi(v.y), h2 = bf_hi(v.z), h3 = bf_hi(v.w);
        size_t ui = gbase / 2 + (size_t)lin * 2;
        *(uint2*)(nvh + ui) = make_uint2(pack2bf(v.x, v.y), pack2bf(v.z, v.w));
        *(uint2*)(nvl + ui) =
            make_uint2(pack2bf(v.x - h0, v.y - h1), pack2bf(v.z - h2, v.w - h3));
    }
    __syncthreads();

    float u[24];
#pragma unroll
    for (int t = 0; t < 24; t++) u[t] = g_U[w * ND + t * 32 + lane];
    const float ch = g_c[w];

    for (int j = 0; j < 8; j++) {
        float acc = 0.f;
#pragma unroll
        for (int t = 0; t < 24; t++) acc += s_nv[j][t * 32 + lane] * u[t];
#pragma unroll
        for (int off = 16; off > 0; off >>= 1)
            acc += __shfl_xor_sync(0xFFFFFFFF, acc, off);
        if (lane == 0) g_sk[((size_t)b * NH + w) * NS + j0 + j] = acc + ch;
    }
}

// ---------------------------------------------------------------------------
// attention: block per (b,h), 256 threads; V cached in smem; writes hi/lo A.
// ---------------------------------------------------------------------------
__global__ __launch_bounds__(256)
void attn_kernel(const float* __restrict__ desc, const float* __restrict__ Wa)
{
    const int b = blockIdx.x / NH;
    const int h = blockIdx.x % NH;
    const int tid = threadIdx.x;
    const int lane = tid & 31, wid = tid >> 5;

    __shared__ float sV[NS * HD];       // 32KB
    __shared__ float p[NS];
    __shared__ float red[256];
    __shared__ float vsum[HD];
    __shared__ float s_we[HD];
    __shared__ float s_part[8];

    if (tid < HD) s_we[tid] = Wa[2 * HD + tid];
    __syncthreads();

    const float* Vp = g_V + (size_t)b * NS * ND + h * HD;

    // logits (tid = j, 1..127)
    float l = -1e30f;
    if (tid >= 1 && tid < NS) {
        const float* er = desc + ((size_t)b * (NS - 1) + (tid - 1)) * ND + h * HD;
        float acc = 0.f;
#pragma unroll 8
        for (int d = 0; d < HD; d++) acc += er[d] * s_we[d];
        l = acc + g_sk[((size_t)b * NH + h) * NS + tid];
    }
    float wm = l;
#pragma unroll
    for (int off = 16; off > 0; off >>= 1)
        wm = fmaxf(wm, __shfl_xor_sync(0xFFFFFFFF, wm, off));
    if (lane == 0 && wid < 4) s_part[wid] = wm;
    __syncthreads();
    const float m = fmaxf(fmaxf(s_part[0], s_part[1]), fmaxf(s_part[2], s_part[3]));

    const float pe = (tid >= 1 && tid < NS) ? expf(l - m) : 0.f;
    if (tid < NS) p[tid] = pe;
    float ws = pe;
#pragma unroll
    for (int off = 16; off > 0; off >>= 1)
        ws += __shfl_xor_sync(0xFFFFFFFF, ws, off);
    if (lane == 0 && wid < 4) s_part[wid + 4] = ws;
    __syncthreads();
    const float Sall = s_part[4] + s_part[5] + s_part[6] + s_part[7];

    // Vsum + cache V tile in smem
    const int d = tid & 63;
    const int q = tid >> 6;
    if (tid < HD) sV[d] = Vp[d];       // row 0 (only multiplied by p[0]=0, but avoid NaN)
    {
        float acc = 0.f;
#pragma unroll 4
        for (int j = 1 + q; j < NS; j += 4) {
            float v = Vp[(size_t)j * ND + d];
            sV[j * HD + d] = v;
            acc += p[j] * v;
        }
        red[tid] = acc;
        __syncthreads();
        if (tid < HD)
            vsum[tid] = red[tid] + red[tid + 64] + red[tid + 128] + red[tid + 192];
        __syncthreads();
    }

    const float vs = vsum[d];
    __nv_bfloat16* Ah = g_Ah + (size_t)b * NS * ND + h * HD + d;
    __nv_bfloat16* Al = g_Al + (size_t)b * NS * ND + h * HD + d;
#pragma unroll 4
    for (int i = q; i < NS; i += 4) {
        const float pi = p[i];
        const float val = __fdividef(vs - pi * sV[i * HD + d], Sall - pi);
        const float hi = bf_hi(val);
        Ah[(size_t)i * ND] = __float2bfloat16(val);
        Al[(size_t)i * ND] = __float2bfloat16(val - hi);
    }
}

// ---------------------------------------------------------------------------
extern "C" void kernel_launch(void* const* d_in, const int* in_sizes, int n_in,
                              void* d_out, int out_size)
{
    const float* desc = (const float*)d_in[0];
    const float* nv   = (const float*)d_in[1];
    // d_in[2]=Wq, d_in[3]=bq dead; d_in[11]=ba dead (cancel in softmax)
    const float* Wk   = (const float*)d_in[4];
    const float* bk   = (const float*)d_in[5];
    const float* Wv   = (const float*)d_in[6];
    const float* bv   = (const float*)d_in[7];
    const float* Wo   = (const float*)d_in[8];
    const float* bo   = (const float*)d_in[9];
    const float* Wa   = (const float*)d_in[10];
    float* out = (float*)d_out;

    cudaFuncSetAttribute(gemm_cp, cudaFuncAttributeMaxDynamicSharedMemorySize, 2 * STG);

    float* pV; cudaGetSymbolAddress((void**)&pV, g_V);
    __nv_bfloat16 *pnvh, *pnvl, *pAh, *pAl, *pWvh, *pWvl, *pWoh, *pWol;
    cudaGetSymbolAddress((void**)&pnvh, g_nvh);
    cudaGetSymbolAddress((void**)&pnvl, g_nvl);
    cudaGetSymbolAddress((void**)&pAh, g_Ah);
    cudaGetSymbolAddress((void**)&pAl, g_Al);
    cudaGetSymbolAddress((void**)&pWvh, g_Wvh);
    cudaGetSymbolAddress((void**)&pWvl, g_Wvl);
    cudaGetSymbolAddress((void**)&pWoh, g_Woh);
    cudaGetSymbolAddress((void**)&pWol, g_Wol);

    cvtw_kernel<<<dim3(ND * ND / 1024, 2), 256>>>(Wv, Wo);
    prep_kernel<<<NH, 256>>>(Wk, bk, Wa);
    score_cvt_kernel<<<dim3(NB, 16), 384>>>(nv);

    dim3 ggrid(ND / 64, NM / 128);             // 12 x 32 = 384 CTAs
    gemm_cp<<<ggrid, 256, 2 * STG>>>(pnvh, pnvl, pWvh, pWvl, bv, pV);
    attn_kernel<<<NB * NH, 256>>>(desc, Wa);
    gemm_cp<<<ggrid, 256, 2 * STG>>>(pAh, pAl, pWoh, pWol, bo, out);
}

// round 5
// speedup vs baseline: 4.8568x; 1.1803x over previous
#include <cuda_runtime.h>
#include <cuda_bf16.h>
#include <cstdint>

#define NB 32
#define NS 128
#define ND 768
#define NH 12
#define HD 64
#define NM (NB*NS)   // 4096

// Scratch
__device__ __nv_bfloat16 g_nvh[NB*NS*ND];             // nv hi/lo bf16
__device__ __nv_bfloat16 g_nvl[NB*NS*ND];
__device__ __nv_bfloat16 g_Ah[NB*NS*ND];              // attn out hi/lo
__device__ __nv_bfloat16 g_Al[NB*NS*ND];
__device__ __nv_bfloat16 g_Wvh[ND*ND], g_Wvl[ND*ND];
__device__ __nv_bfloat16 g_Woh[ND*ND], g_Wol[ND*ND];
__device__ float g_U[NH*ND];
__device__ float g_c[NH];
__device__ float g_lg[NB*NH*NS];   // logits sk + e
__device__ float g_p[NB*NH*NS];    // softmax numerators
__device__ float g_S[NB*NH];       // softmax denominators

// ---------------------------------------------------------------------------
__device__ __forceinline__ uint32_t smem_u32(const void* p) {
    uint32_t a;
    asm("{ .reg .u64 t; cvta.to.shared.u64 t, %1; cvt.u32.u64 %0, t; }"
        : "=r"(a) : "l"(p));
    return a;
}
#define SWZ(o) ((o) ^ (((o) >> 3) & 0x70))

__device__ __forceinline__ void ldm_x4(uint32_t* r, uint32_t addr) {
    asm volatile("ldmatrix.sync.aligned.m8n8.x4.shared.b16 {%0,%1,%2,%3}, [%4];"
                 : "=r"(r[0]), "=r"(r[1]), "=r"(r[2]), "=r"(r[3]) : "r"(addr));
}
__device__ __forceinline__ void mma_bf16(float* d, const uint32_t* a, const uint32_t* b) {
    asm volatile(
        "mma.sync.aligned.m16n8k16.row.col.f32.bf16.bf16.f32 "
        "{%0,%1,%2,%3}, {%4,%5,%6,%7}, {%8,%9}, {%0,%1,%2,%3};"
        : "+f"(d[0]), "+f"(d[1]), "+f"(d[2]), "+f"(d[3])
        : "r"(a[0]), "r"(a[1]), "r"(a[2]), "r"(a[3]), "r"(b[0]), "r"(b[1]));
}
__device__ __forceinline__ void cpa16(uint32_t dst, const void* src) {
    asm volatile("cp.async.cg.shared.global [%0], [%1], 16;"
                 :: "r"(dst), "l"(src) : "memory");
}
__device__ __forceinline__ void cpa_commit() {
    asm volatile("cp.async.commit_group;" ::: "memory");
}
__device__ __forceinline__ void cpa_wait0() {
    asm volatile("cp.async.wait_group 0;" ::: "memory");
}
__device__ __forceinline__ uint32_t pack2bf(float a, float b) {
    __nv_bfloat162 t = __floats2bfloat162_rn(a, b);
    return *(uint32_t*)&t;
}
__device__ __forceinline__ float bf_hi(float x) {
    return __bfloat162float(__float2bfloat16(x));
}

// ---------------------------------------------------------------------------
// Shared GEMM mainloop: acc = X * W^T  (X/W hi-lo bf16 split, 3-pass)
// CTA tile 128(M)x64(N), BK=64, 256 threads (8 warps, 32x32 each).
// Smem stage 48KB: A_hi@0 A_lo@16K B_hi@32K B_lo@40K; double buffered.
// ---------------------------------------------------------------------------
#define STG 49152
__device__ __forceinline__ void gemm_main(
    const __nv_bfloat16* __restrict__ Xh, const __nv_bfloat16* __restrict__ Xl,
    const __nv_bfloat16* __restrict__ Wh, const __nv_bfloat16* __restrict__ Wl,
    char* sm, int bm, int bn, float acc[2][4][4])
{
    const int tid = threadIdx.x;
    const int lane = tid & 31, w = tid >> 5;
    const uint32_t smb = smem_u32(sm);
    const int wm = w >> 1, wn = w & 1;

    const uint32_t a_row = (uint32_t)(wm * 32 + (lane & 15));
    const uint32_t a_kh  = (uint32_t)((lane >> 4) << 4);
    const uint32_t b_row = (uint32_t)(wn * 32 + (lane & 7) + ((lane >> 4) << 3));
    const uint32_t b_kh  = (uint32_t)(((lane >> 3) & 1) << 4);

#pragma unroll
    for (int mt = 0; mt < 2; mt++)
#pragma unroll
        for (int nt = 0; nt < 4; nt++)
#pragma unroll
            for (int i = 0; i < 4; i++) acc[mt][nt][i] = 0.f;

    auto ISSUE = [&](int c, int s) {
        const uint32_t sb = smb + s * STG;
        const int k0 = c * 64;
#pragma unroll
        for (int it = 0; it < 4; it++) {
            const int L = tid + it * 256;
            const int r = L >> 3, k8 = (L & 7);
            const uint32_t so = SWZ((uint32_t)(r * 128 + k8 * 16));
            const size_t go = (size_t)(bm + r) * ND + k0 + k8 * 8;
            cpa16(sb + so,         Xh + go);
            cpa16(sb + 16384 + so, Xl + go);
        }
#pragma unroll
        for (int it = 0; it < 2; it++) {
            const int L = tid + it * 256;
            const int r = L >> 3, k8 = (L & 7);
            const uint32_t so = SWZ((uint32_t)(r * 128 + k8 * 16));
            const size_t go = (size_t)(bn + r) * ND + k0 + k8 * 8;
            cpa16(sb + 32768 + so, Wh + go);
            cpa16(sb + 40960 + so, Wl + go);
        }
        cpa_commit();
    };

    ISSUE(0, 0);
    for (int c = 0; c < 12; c++) {
        cpa_wait0();
        __syncthreads();
        if (c < 11) ISSUE(c + 1, (c + 1) & 1);
        const uint32_t sb = smb + (c & 1) * STG;

#pragma unroll
        for (int ks = 0; ks < 4; ks++) {
            uint32_t ah[2][4], al[2][4], bh[2][4], bl[2][4];
#pragma unroll
            for (int mt = 0; mt < 2; mt++) {
                const uint32_t byo = (a_row + mt * 16) * 128 + ks * 32 + a_kh;
                ldm_x4(ah[mt], sb + SWZ(byo));
                ldm_x4(al[mt], sb + 16384 + SWZ(byo));
            }
#pragma unroll
            for (int nt2 = 0; nt2 < 2; nt2++) {
                const uint32_t byo = (b_row + nt2 * 16) * 128 + ks * 32 + b_kh;
                ldm_x4(bh[nt2], sb + 32768 + SWZ(byo));
                ldm_x4(bl[nt2], sb + 40960 + SWZ(byo));
            }
#pragma unroll
            for (int mt = 0; mt < 2; mt++)
#pragma unroll
                for (int nt = 0; nt < 4; nt++) {
                    const uint32_t* bhp = &bh[nt >> 1][(nt & 1) * 2];
                    const uint32_t* blp = &bl[nt >> 1][(nt & 1) * 2];
                    mma_bf16(acc[mt][nt], ah[mt], bhp);
                    mma_bf16(acc[mt][nt], ah[mt], blp);
                    mma_bf16(acc[mt][nt], al[mt], bhp);
                }
        }
        __syncthreads();
    }
}

// ---------------------------------------------------------------------------
// V projection GEMM with FUSED attention epilogue.
// CTA (bx=h, by=b): computes V[b, 0:128, h*64:(h+1)*64] then
//   A[b,i,h,d] = (Vsum[d] - p[i] V[i,d]) / (S - p[i]),  Vsum = sum_j p[j]V[j,:]
// writes A as hi/lo bf16 into g_Ah/g_Al.
// ---------------------------------------------------------------------------
__global__ __launch_bounds__(256, 2)
void gemm_v_attn(const __nv_bfloat16* __restrict__ Xh, const __nv_bfloat16* __restrict__ Xl,
                 const __nv_bfloat16* __restrict__ Wh, const __nv_bfloat16* __restrict__ Wl,
                 const float* __restrict__ bv)
{
    extern __shared__ __align__(1024) char sm[];
    __shared__ float sp[NS];
    __shared__ float sred[256];
    __shared__ float svs[HD];

    const int h = blockIdx.x, b = blockIdx.y;
    const int bm = b * 128, bn = h * 64;
    const int tid = threadIdx.x;
    const int lane = tid & 31, w = tid >> 5;
    const int wm = w >> 1, wn = w & 1;

    float acc[2][4][4];
    gemm_main(Xh, Xl, Wh, Wl, sm, bm, bn, acc);

    // stage V tile (+bias) to smem, fetch p
    float* sVt = (float*)sm;                      // 128 x 64 fp32 (32KB)
    if (tid < NS) sp[tid] = g_p[((size_t)b * NH + h) * NS + tid];
    const int r_base = wm * 32 + (lane >> 2);
    const int c_base = wn * 32 + ((lane & 3) << 1);
#pragma unroll
    for (int mt = 0; mt < 2; mt++)
#pragma unroll
        for (int nt = 0; nt < 4; nt++) {
            const int c = c_base + nt * 8;
            const float b0 = bv[bn + c], b1 = bv[bn + c + 1];
            const int r0 = r_base + mt * 16;
            *(float2*)&sVt[r0 * 64 + c] =
                make_float2(acc[mt][nt][0] + b0, acc[mt][nt][1] + b1);
            *(float2*)&sVt[(r0 + 8) * 64 + c] =
                make_float2(acc[mt][nt][2] + b0, acc[mt][nt][3] + b1);
        }
    __syncthreads();

    const float S = g_S[b * NH + h];
    const int d = tid & 63;
    const int q = tid >> 6;
    float av = 0.f;
#pragma unroll 4
    for (int j = q; j < NS; j += 4) av += sp[j] * sVt[j * 64 + d];   // p[0]=0
    sred[tid] = av;
    __syncthreads();
    if (tid < HD)
        svs[tid] = sred[tid] + sred[tid + 64] + sred[tid + 128] + sred[tid + 192];
    __syncthreads();

    const float vs = svs[d];
    __nv_bfloat16* Ah = g_Ah + ((size_t)b * NS) * ND + bn + d;
    __nv_bfloat16* Al = g_Al + ((size_t)b * NS) * ND + bn + d;
#pragma unroll 4
    for (int i = q; i < NS; i += 4) {
        const float pi = sp[i];
        const float val = __fdividef(vs - pi * sVt[i * 64 + d], S - pi);
        const float hi = bf_hi(val);
        Ah[(size_t)i * ND] = __float2bfloat16(val);
        Al[(size_t)i * ND] = __float2bfloat16(val - hi);
    }
}

// ---------------------------------------------------------------------------
// Output projection GEMM (plain epilogue: bias + fp32 store)
// ---------------------------------------------------------------------------
__global__ __launch_bounds__(256, 2)
void gemm_o(const __nv_bfloat16* __restrict__ Xh, const __nv_bfloat16* __restrict__ Xl,
            const __nv_bfloat16* __restrict__ Wh, const __nv_bfloat16* __restrict__ Wl,
            const float* __restrict__ bias, float* __restrict__ C)
{
    extern __shared__ __align__(1024) char sm[];
    const int bm = blockIdx.y * 128, bn = blockIdx.x * 64;
    const int tid = threadIdx.x;
    const int lane = tid & 31, w = tid >> 5;
    const int wm = w >> 1, wn = w & 1;

    float acc[2][4][4];
    gemm_main(Xh, Xl, Wh, Wl, sm, bm, bn, acc);

    const int erow = bm + wm * 32 + (lane >> 2);
    const int ecol0 = bn + wn * 32 + ((lane & 3) << 1);
#pragma unroll
    for (int mt = 0; mt < 2; mt++)
#pragma unroll
        for (int nt = 0; nt < 4; nt++) {
            const int col = ecol0 + nt * 8;
            const float b0 = bias[col], b1 = bias[col + 1];
            const int r0 = erow + mt * 16;
            *(float2*)(C + (size_t)r0 * ND + col) =
                make_float2(acc[mt][nt][0] + b0, acc[mt][nt][1] + b1);
            *(float2*)(C + (size_t)(r0 + 8) * ND + col) =
                make_float2(acc[mt][nt][2] + b0, acc[mt][nt][3] + b1);
        }
}

// ---------------------------------------------------------------------------
// Weight split: Wv, Wo -> hi/lo bf16
// ---------------------------------------------------------------------------
__global__ void cvtw_kernel(const float* __restrict__ Wv, const float* __restrict__ Wo)
{
    const int lin = blockIdx.x * 256 + threadIdx.x;
    const float* src = blockIdx.y ? Wo : Wv;
    uint32_t* hi = (uint32_t*)(blockIdx.y ? g_Woh : g_Wvh);
    uint32_t* lo = (uint32_t*)(blockIdx.y ? g_Wol : g_Wvl);
    float4 v = *(const float4*)(src + (size_t)lin * 4);
    float h0 = bf_hi(v.x), h1 = bf_hi(v.y), h2 = bf_hi(v.z), h3 = bf_hi(v.w);
    *(uint2*)(hi + (size_t)lin * 2) = make_uint2(pack2bf(v.x, v.y), pack2bf(v.z, v.w));
    *(uint2*)(lo + (size_t)lin * 2) =
        make_uint2(pack2bf(v.x - h0, v.y - h1), pack2bf(v.z - h2, v.w - h3));
}

// ---------------------------------------------------------------------------
// prep: g_U[h][k] = sum_d wk_a[d]*Wk[h*64+d][k];  g_c[h] = wk_a . bk[h*64:]
// ---------------------------------------------------------------------------
__global__ void prep_kernel(const float* __restrict__ Wk,
                            const float* __restrict__ bk,
                            const float* __restrict__ Wa)
{
    const int h = blockIdx.x;
    const int tid = threadIdx.x;
    __shared__ float swk[HD];
    if (tid < HD) swk[tid] = Wa[HD + tid];
    __syncthreads();
    for (int k = tid; k < ND; k += 256) {
        float a = 0.f;
#pragma unroll 8
        for (int d = 0; d < HD; d++)
            a += swk[d] * Wk[(size_t)(h * HD + d) * ND + k];
        g_U[h * ND + k] = a;
    }
    if (tid == 0) {
        float cc = 0.f;
        for (int d = 0; d < HD; d++) cc += swk[d] * bk[h * HD + d];
        g_c[h] = cc;
    }
}

// ---------------------------------------------------------------------------
// score + nv split + full logits: g_lg[b,h,j] = nv[b,j].u_h + c_h + desc[b,j-1,h].we
// block = (b, 8-row j tile); 12 warps = 12 heads
// ---------------------------------------------------------------------------
__global__ __launch_bounds__(384)
void score_cvt_kernel(const float* __restrict__ nv,
                      const float* __restrict__ desc,
                      const float* __restrict__ Wa)
{
    __shared__ float s_nv[8][ND];
    __shared__ float s_ds[8][ND];
    const int b = blockIdx.x;
    const int j0 = blockIdx.y * 8;
    const int tid = threadIdx.x;
    const int w = tid >> 5, lane = tid & 31;

    const size_t gbase = ((size_t)b * NS + j0) * ND;
    const float* src = nv + gbase;
    uint32_t* nvh = (uint32_t*)g_nvh;
    uint32_t* nvl = (uint32_t*)g_nvl;
#pragma unroll
    for (int it = 0; it < 4; it++) {
        int lin = tid + it * 384;                 // float4 idx in 8x768 tile
        float4 v = *(const float4*)(src + lin * 4);
        *(float4*)(&s_nv[0][0] + lin * 4) = v;
        float h0 = bf_hi(v.x), h1 = bf_hi(v.y), h2 = bf_hi(v.z), h3 = bf_hi(v.w);
        size_t ui = gbase / 2 + (size_t)lin * 2;
        *(uint2*)(nvh + ui) = make_uint2(pack2bf(v.x, v.y), pack2bf(v.z, v.w));
        *(uint2*)(nvl + ui) =
            make_uint2(pack2bf(v.x - h0, v.y - h1), pack2bf(v.z - h2, v.w - h3));
        // desc rows: local row r holds desc[b, j0+r-1]
        int r = lin / 192, c4 = lin % 192;
        int drow = j0 + r - 1;
        float4 dv = (drow >= 0)
            ? *(const float4*)(desc + ((size_t)b * (NS - 1) + drow) * ND + c4 * 4)
            : make_float4(0.f, 0.f, 0.f, 0.f);
        *(float4*)(&s_ds[r][0] + c4 * 4) = dv;
    }
    __syncthreads();

    float u[24];
#pragma unroll
    for (int t = 0; t < 24; t++) u[t] = g_U[w * ND + t * 32 + lane];
    const float ch = g_c[w];
    const float we0 = Wa[2 * HD + lane], we1 = Wa[2 * HD + 32 + lane];

    for (int j = 0; j < 8; j++) {
        float acc = 0.f;
#pragma unroll
        for (int t = 0; t < 24; t++) acc += s_nv[j][t * 32 + lane] * u[t];
        // e-score: desc slice for head w
        acc += s_ds[j][w * 64 + lane] * we0 + s_ds[j][w * 64 + 32 + lane] * we1;
#pragma unroll
        for (int off = 16; off > 0; off >>= 1)
            acc += __shfl_xor_sync(0xFFFFFFFF, acc, off);
        if (lane == 0)
            g_lg[((size_t)b * NH + w) * NS + j0 + j] = (j0 + j >= 1) ? acc + ch : 0.f;
    }
}

// ---------------------------------------------------------------------------
// softmax over j per (b,h): writes g_p, g_S
// ---------------------------------------------------------------------------
__global__ __launch_bounds__(128)
void softmax_kernel()
{
    const int bh = blockIdx.x;
    const int tid = threadIdx.x;       // = j
    const int lane = tid & 31, wid = tid >> 5;
    __shared__ float s_part[8];

    const float l = (tid >= 1) ? g_lg[(size_t)bh * NS + tid] : -1e30f;
    float wm = l;
#pragma unroll
    for (int off = 16; off > 0; off >>= 1)
        wm = fmaxf(wm, __shfl_xor_sync(0xFFFFFFFF, wm, off));
    if (lane == 0) s_part[wid] = wm;
    __syncthreads();
    const float m = fmaxf(fmaxf(s_part[0], s_part[1]), fmaxf(s_part[2], s_part[3]));

    const float pe = (tid >= 1) ? expf(l - m) : 0.f;
    float ws = pe;
#pragma unroll
    for (int off = 16; off > 0; off >>= 1)
        ws += __shfl_xor_sync(0xFFFFFFFF, ws, off);
    if (lane == 0) s_part[4 + wid] = ws;
    __syncthreads();

    g_p[(size_t)bh * NS + tid] = pe;
    if (tid == 0)
        g_S[bh] = s_part[4] + s_part[5] + s_part[6] + s_part[7];
}

// ---------------------------------------------------------------------------
extern "C" void kernel_launch(void* const* d_in, const int* in_sizes, int n_in,
                              void* d_out, int out_size)
{
    const float* desc = (const float*)d_in[0];
    const float* nv   = (const float*)d_in[1];
    // d_in[2]=Wq, d_in[3]=bq dead; d_in[11]=ba dead (cancel in softmax)
    const float* Wk   = (const float*)d_in[4];
    const float* bk   = (const float*)d_in[5];
    const float* Wv   = (const float*)d_in[6];
    const float* bv   = (const float*)d_in[7];
    const float* Wo   = (const float*)d_in[8];
    const float* bo   = (const float*)d_in[9];
    const float* Wa   = (const float*)d_in[10];
    float* out = (float*)d_out;

    cudaFuncSetAttribute(gemm_v_attn, cudaFuncAttributeMaxDynamicSharedMemorySize, 2 * STG);
    cudaFuncSetAttribute(gemm_o, cudaFuncAttributeMaxDynamicSharedMemorySize, 2 * STG);

    __nv_bfloat16 *pnvh, *pnvl, *pAh, *pAl, *pWvh, *pWvl, *pWoh, *pWol;
    cudaGetSymbolAddress((void**)&pnvh, g_nvh);
    cudaGetSymbolAddress((void**)&pnvl, g_nvl);
    cudaGetSymbolAddress((void**)&pAh, g_Ah);
    cudaGetSymbolAddress((void**)&pAl, g_Al);
    cudaGetSymbolAddress((void**)&pWvh, g_Wvh);
    cudaGetSymbolAddress((void**)&pWvl, g_Wvl);
    cudaGetSymbolAddress((void**)&pWoh, g_Woh);
    cudaGetSymbolAddress((void**)&pWol, g_Wol);

    cvtw_kernel<<<dim3(ND * ND / 1024, 2), 256>>>(Wv, Wo);
    prep_kernel<<<NH, 256>>>(Wk, bk, Wa);
    score_cvt_kernel<<<dim3(NB, 16), 384>>>(nv, desc, Wa);
    softmax_kernel<<<NB * NH, 128>>>();

    dim3 ggrid(ND / 64, NM / 128);             // 12 x 32 = 384 CTAs
    gemm_v_attn<<<ggrid, 256, 2 * STG>>>(pnvh, pnvl, pWvh, pWvl, bv);
    gemm_o<<<ggrid, 256, 2 * STG>>>(pAh, pAl, pWoh, pWol, bo, out);
}

// round 6
// speedup vs baseline: 4.8593x; 1.0005x over previous
#include <cuda_runtime.h>
#include <cuda_bf16.h>
#include <cstdint>

#define NB 32
#define NS 128
#define ND 768
#define NH 12
#define HD 64
#define NM (NB*NS)   // 4096

// Scratch
__device__ __nv_bfloat16 g_nvh[NB*NS*ND];
__device__ __nv_bfloat16 g_nvl[NB*NS*ND];
__device__ __nv_bfloat16 g_Ah[NB*NS*ND];
__device__ __nv_bfloat16 g_Al[NB*NS*ND];
__device__ __nv_bfloat16 g_Wvh[ND*ND], g_Wvl[ND*ND];
__device__ __nv_bfloat16 g_Woh[ND*ND], g_Wol[ND*ND];
__device__ float g_U[NH*ND];
__device__ float g_c[NH];
__device__ float g_lg[NB*NH*NS];       // logits
__device__ unsigned g_flag[NB];        // producer completion counters

// ---------------------------------------------------------------------------
__device__ __forceinline__ uint32_t smem_u32(const void* p) {
    uint32_t a;
    asm("{ .reg .u64 t; cvta.to.shared.u64 t, %1; cvt.u32.u64 %0, t; }"
        : "=r"(a) : "l"(p));
    return a;
}
#define SWZ(o) ((o) ^ (((o) >> 3) & 0x70))

__device__ __forceinline__ void ldm_x4(uint32_t* r, uint32_t addr) {
    asm volatile("ldmatrix.sync.aligned.m8n8.x4.shared.b16 {%0,%1,%2,%3}, [%4];"
                 : "=r"(r[0]), "=r"(r[1]), "=r"(r[2]), "=r"(r[3]) : "r"(addr));
}
__device__ __forceinline__ void mma_bf16(float* d, const uint32_t* a, const uint32_t* b) {
    asm volatile(
        "mma.sync.aligned.m16n8k16.row.col.f32.bf16.bf16.f32 "
        "{%0,%1,%2,%3}, {%4,%5,%6,%7}, {%8,%9}, {%0,%1,%2,%3};"
        : "+f"(d[0]), "+f"(d[1]), "+f"(d[2]), "+f"(d[3])
        : "r"(a[0]), "r"(a[1]), "r"(a[2]), "r"(a[3]), "r"(b[0]), "r"(b[1]));
}
__device__ __forceinline__ void cpa16(uint32_t dst, const void* src) {
    asm volatile("cp.async.cg.shared.global [%0], [%1], 16;"
                 :: "r"(dst), "l"(src) : "memory");
}
__device__ __forceinline__ void cpa_commit() {
    asm volatile("cp.async.commit_group;" ::: "memory");
}
__device__ __forceinline__ void cpa_wait0() {
    asm volatile("cp.async.wait_group 0;" ::: "memory");
}
__device__ __forceinline__ uint32_t pack2bf(float a, float b) {
    __nv_bfloat162 t = __floats2bfloat162_rn(a, b);
    return *(uint32_t*)&t;
}
__device__ __forceinline__ float bf_hi(float x) {
    return __bfloat162float(__float2bfloat16(x));
}
__device__ __forceinline__ unsigned ld_acq(const unsigned* p) {
    unsigned v;
    asm volatile("ld.acquire.gpu.global.u32 %0, [%1];" : "=r"(v) : "l"(p));
    return v;
}

// ---------------------------------------------------------------------------
// GEMM mainloop: acc = X * W^T (hi/lo bf16 split, 3-pass)
// 128(M)x64(N) tile, BK=64, 256 thr, double-buffered cp.async.
// ---------------------------------------------------------------------------
#define STG 49152
__device__ __forceinline__ void gemm_main(
    const __nv_bfloat16* __restrict__ Xh, const __nv_bfloat16* __restrict__ Xl,
    const __nv_bfloat16* __restrict__ Wh, const __nv_bfloat16* __restrict__ Wl,
    char* sm, int bm, int bn, float acc[2][4][4])
{
    const int tid = threadIdx.x;
    const int lane = tid & 31, w = tid >> 5;
    const uint32_t smb = smem_u32(sm);
    const int wm = w >> 1, wn = w & 1;

    const uint32_t a_row = (uint32_t)(wm * 32 + (lane & 15));
    const uint32_t a_kh  = (uint32_t)((lane >> 4) << 4);
    const uint32_t b_row = (uint32_t)(wn * 32 + (lane & 7) + ((lane >> 4) << 3));
    const uint32_t b_kh  = (uint32_t)(((lane >> 3) & 1) << 4);

#pragma unroll
    for (int mt = 0; mt < 2; mt++)
#pragma unroll
        for (int nt = 0; nt < 4; nt++)
#pragma unroll
            for (int i = 0; i < 4; i++) acc[mt][nt][i] = 0.f;

    auto ISSUE = [&](int c, int s) {
        const uint32_t sb = smb + s * STG;
        const int k0 = c * 64;
#pragma unroll
        for (int it = 0; it < 4; it++) {
            const int L = tid + it * 256;
            const int r = L >> 3, k8 = (L & 7);
            const uint32_t so = SWZ((uint32_t)(r * 128 + k8 * 16));
            const size_t go = (size_t)(bm + r) * ND + k0 + k8 * 8;
            cpa16(sb + so,         Xh + go);
            cpa16(sb + 16384 + so, Xl + go);
        }
#pragma unroll
        for (int it = 0; it < 2; it++) {
            const int L = tid + it * 256;
            const int r = L >> 3, k8 = (L & 7);
            const uint32_t so = SWZ((uint32_t)(r * 128 + k8 * 16));
            const size_t go = (size_t)(bn + r) * ND + k0 + k8 * 8;
            cpa16(sb + 32768 + so, Wh + go);
            cpa16(sb + 40960 + so, Wl + go);
        }
        cpa_commit();
    };

    ISSUE(0, 0);
    for (int c = 0; c < 12; c++) {
        cpa_wait0();
        __syncthreads();
        if (c < 11) ISSUE(c + 1, (c + 1) & 1);
        const uint32_t sb = smb + (c & 1) * STG;

#pragma unroll
        for (int ks = 0; ks < 4; ks++) {
            uint32_t ah[2][4], al[2][4], bh[2][4], bl[2][4];
#pragma unroll
            for (int mt = 0; mt < 2; mt++) {
                const uint32_t byo = (a_row + mt * 16) * 128 + ks * 32 + a_kh;
                ldm_x4(ah[mt], sb + SWZ(byo));
                ldm_x4(al[mt], sb + 16384 + SWZ(byo));
            }
#pragma unroll
            for (int nt2 = 0; nt2 < 2; nt2++) {
                const uint32_t byo = (b_row + nt2 * 16) * 128 + ks * 32 + b_kh;
                ldm_x4(bh[nt2], sb + 32768 + SWZ(byo));
                ldm_x4(bl[nt2], sb + 40960 + SWZ(byo));
            }
#pragma unroll
            for (int mt = 0; mt < 2; mt++)
#pragma unroll
                for (int nt = 0; nt < 4; nt++) {
                    const uint32_t* bhp = &bh[nt >> 1][(nt & 1) * 2];
                    const uint32_t* blp = &bl[nt >> 1][(nt & 1) * 2];
                    mma_bf16(acc[mt][nt], ah[mt], bhp);
                    mma_bf16(acc[mt][nt], ah[mt], blp);
                    mma_bf16(acc[mt][nt], al[mt], bhp);
                }
        }
        __syncthreads();
    }
}

// ---------------------------------------------------------------------------
// Mega kernel: bids 0..383 producers (V-proj + softmax + attn epilogue),
//              bids 384..767 consumers (out-proj, gated on flag[b]==12).
// ---------------------------------------------------------------------------
__global__ __launch_bounds__(256, 2)
void mega_gemm(const __nv_bfloat16* __restrict__ nvh, const __nv_bfloat16* __restrict__ nvl,
               const __nv_bfloat16* __restrict__ Wvh, const __nv_bfloat16* __restrict__ Wvl,
               const __nv_bfloat16* __restrict__ Ah,  const __nv_bfloat16* __restrict__ Al,
               const __nv_bfloat16* __restrict__ Woh, const __nv_bfloat16* __restrict__ Wol,
               const float* __restrict__ bv, const float* __restrict__ bo,
               float* __restrict__ out)
{
    extern __shared__ __align__(1024) char sm[];
    __shared__ float sp[NS];
    __shared__ float spart[8];
    __shared__ float sred[256];
    __shared__ float svs[HD];

    const int bid = blockIdx.x;
    const int tid = threadIdx.x;
    const int lane = tid & 31, w = tid >> 5;
    const int wm = w >> 1, wn = w & 1;

    if (bid < 384) {
        // ------------------- PRODUCER: V proj + attention -------------------
        const int h = bid % NH, b = bid / NH;
        const int bm = b * 128, bn = h * 64;

        // inline softmax for row (b,h)
        const float* lg = g_lg + ((size_t)b * NH + h) * NS;
        float l = -1e30f;
        if (tid >= 1 && tid < NS) l = lg[tid];
        float wmx = l;
#pragma unroll
        for (int off = 16; off > 0; off >>= 1)
            wmx = fmaxf(wmx, __shfl_xor_sync(0xFFFFFFFF, wmx, off));
        if (lane == 0 && w < 4) spart[w] = wmx;
        __syncthreads();
        const float m = fmaxf(fmaxf(spart[0], spart[1]), fmaxf(spart[2], spart[3]));
        const float pe = (tid >= 1 && tid < NS) ? expf(l - m) : 0.f;
        if (tid < NS) sp[tid] = pe;
        float ws = pe;
#pragma unroll
        for (int off = 16; off > 0; off >>= 1)
            ws += __shfl_xor_sync(0xFFFFFFFF, ws, off);
        if (lane == 0 && w < 4) spart[4 + w] = ws;
        __syncthreads();

        float acc[2][4][4];
        gemm_main(nvh, nvl, Wvh, Wvl, sm, bm, bn, acc);

        // stage V tile (+bias) into smem
        float* sVt = (float*)sm;
        const int r_base = wm * 32 + (lane >> 2);
        const int c_base = wn * 32 + ((lane & 3) << 1);
#pragma unroll
        for (int mt = 0; mt < 2; mt++)
#pragma unroll
            for (int nt = 0; nt < 4; nt++) {
                const int c = c_base + nt * 8;
                const float b0 = bv[bn + c], b1 = bv[bn + c + 1];
                const int r0 = r_base + mt * 16;
                *(float2*)&sVt[r0 * 64 + c] =
                    make_float2(acc[mt][nt][0] + b0, acc[mt][nt][1] + b1);
                *(float2*)&sVt[(r0 + 8) * 64 + c] =
                    make_float2(acc[mt][nt][2] + b0, acc[mt][nt][3] + b1);
            }
        __syncthreads();

        const float S = spart[4] + spart[5] + spart[6] + spart[7];
        const int d = tid & 63;
        const int q = tid >> 6;
        float av = 0.f;
#pragma unroll 4
        for (int j = q; j < NS; j += 4) av += sp[j] * sVt[j * 64 + d];
        sred[tid] = av;
        __syncthreads();
        if (tid < HD)
            svs[tid] = sred[tid] + sred[tid + 64] + sred[tid + 128] + sred[tid + 192];
        __syncthreads();

        const float vs = svs[d];
        __nv_bfloat16* pAh = g_Ah + ((size_t)b * NS) * ND + bn + d;
        __nv_bfloat16* pAl = g_Al + ((size_t)b * NS) * ND + bn + d;
#pragma unroll 4
        for (int i = q; i < NS; i += 4) {
            const float pi = sp[i];
            const float val = __fdividef(vs - pi * sVt[i * 64 + d], S - pi);
            const float hi = bf_hi(val);
            pAh[(size_t)i * ND] = __float2bfloat16(val);
            pAl[(size_t)i * ND] = __float2bfloat16(val - hi);
        }
        __syncthreads();
        if (tid == 0) {
            __threadfence();
            atomicAdd(&g_flag[b], 1u);
        }
    } else {
        // ------------------- CONSUMER: out projection -----------------------
        const int cid = bid - 384;
        const int bn = (cid % 12) * 64;
        const int b  = cid / 12;
        const int bm = b * 128;

        if (tid == 0) {
            while (ld_acq(&g_flag[b]) < 12u) __nanosleep(64);
        }
        __syncthreads();

        float acc[2][4][4];
        gemm_main(Ah, Al, Woh, Wol, sm, bm, bn, acc);

        const int erow = bm + wm * 32 + (lane >> 2);
        const int ecol0 = bn + wn * 32 + ((lane & 3) << 1);
#pragma unroll
        for (int mt = 0; mt < 2; mt++)
#pragma unroll
            for (int nt = 0; nt < 4; nt++) {
                const int col = ecol0 + nt * 8;
                const float b0 = bo[col], b1 = bo[col + 1];
                const int r0 = erow + mt * 16;
                *(float2*)(out + (size_t)r0 * ND + col) =
                    make_float2(acc[mt][nt][0] + b0, acc[mt][nt][1] + b1);
                *(float2*)(out + (size_t)(r0 + 8) * ND + col) =
                    make_float2(acc[mt][nt][2] + b0, acc[mt][nt][3] + b1);
            }
    }
}

// ---------------------------------------------------------------------------
// Weight split: Wv, Wo -> hi/lo bf16
// ---------------------------------------------------------------------------
__global__ void cvtw_kernel(const float* __restrict__ Wv, const float* __restrict__ Wo)
{
    const int lin = blockIdx.x * 256 + threadIdx.x;
    const float* src = blockIdx.y ? Wo : Wv;
    uint32_t* hi = (uint32_t*)(blockIdx.y ? g_Woh : g_Wvh);
    uint32_t* lo = (uint32_t*)(blockIdx.y ? g_Wol : g_Wvl);
    float4 v = *(const float4*)(src + (size_t)lin * 4);
    float h0 = bf_hi(v.x), h1 = bf_hi(v.y), h2 = bf_hi(v.z), h3 = bf_hi(v.w);
    *(uint2*)(hi + (size_t)lin * 2) = make_uint2(pack2bf(v.x, v.y), pack2bf(v.z, v.w));
    *(uint2*)(lo + (size_t)lin * 2) =
        make_uint2(pack2bf(v.x - h0, v.y - h1), pack2bf(v.z - h2, v.w - h3));
}

// ---------------------------------------------------------------------------
__global__ void prep_kernel(const float* __restrict__ Wk,
                            const float* __restrict__ bk,
                            const float* __restrict__ Wa)
{
    const int h = blockIdx.x;
    const int tid = threadIdx.x;
    __shared__ float swk[HD];
    if (tid < HD) swk[tid] = Wa[HD + tid];
    __syncthreads();
    for (int k = tid; k < ND; k += 256) {
        float a = 0.f;
#pragma unroll 8
        for (int d = 0; d < HD; d++)
            a += swk[d] * Wk[(size_t)(h * HD + d) * ND + k];
        g_U[h * ND + k] = a;
    }
    if (tid == 0) {
        float cc = 0.f;
        for (int d = 0; d < HD; d++) cc += swk[d] * bk[h * HD + d];
        g_c[h] = cc;
    }
}

// ---------------------------------------------------------------------------
// score + nv split + full logits
// ---------------------------------------------------------------------------
__global__ __launch_bounds__(384)
void score_cvt_kernel(const float* __restrict__ nv,
                      const float* __restrict__ desc,
                      const float* __restrict__ Wa)
{
    __shared__ float s_nv[8][ND];
    __shared__ float s_ds[8][ND];
    const int b = blockIdx.x;
    const int j0 = blockIdx.y * 8;
    const int tid = threadIdx.x;
    const int w = tid >> 5, lane = tid & 31;

    const size_t gbase = ((size_t)b * NS + j0) * ND;
    const float* src = nv + gbase;
    uint32_t* nvh = (uint32_t*)g_nvh;
    uint32_t* nvl = (uint32_t*)g_nvl;
#pragma unroll
    for (int it = 0; it < 4; it++) {
        int lin = tid + it * 384;
        float4 v = *(const float4*)(src + lin * 4);
        *(float4*)(&s_nv[0][0] + lin * 4) = v;
        float h0 = bf_hi(v.x), h1 = bf_hi(v.y), h2 = bf_hi(v.z), h3 = bf_hi(v.w);
        size_t ui = gbase / 2 + (size_t)lin * 2;
        *(uint2*)(nvh + ui) = make_uint2(pack2bf(v.x, v.y), pack2bf(v.z, v.w));
        *(uint2*)(nvl + ui) =
            make_uint2(pack2bf(v.x - h0, v.y - h1), pack2bf(v.z - h2, v.w - h3));
        int r = lin / 192, c4 = lin % 192;
        int drow = j0 + r - 1;
        float4 dv = (drow >= 0)
            ? *(const float4*)(desc + ((size_t)b * (NS - 1) + drow) * ND + c4 * 4)
            : make_float4(0.f, 0.f, 0.f, 0.f);
        *(float4*)(&s_ds[r][0] + c4 * 4) = dv;
    }
    __syncthreads();

    float u[24];
#pragma unroll
    for (int t = 0; t < 24; t++) u[t] = g_U[w * ND + t * 32 + lane];
    const float ch = g_c[w];
    const float we0 = Wa[2 * HD + lane], we1 = Wa[2 * HD + 32 + lane];

    for (int j = 0; j < 8; j++) {
        float acc = 0.f;
#pragma unroll
        for (int t = 0; t < 24; t++) acc += s_nv[j][t * 32 + lane] * u[t];
        acc += s_ds[j][w * 64 + lane] * we0 + s_ds[j][w * 64 + 32 + lane] * we1;
#pragma unroll
        for (int off = 16; off > 0; off >>= 1)
            acc += __shfl_xor_sync(0xFFFFFFFF, acc, off);
        if (lane == 0)
            g_lg[((size_t)b * NH + w) * NS + j0 + j] = (j0 + j >= 1) ? acc + ch : 0.f;
    }
}

// ---------------------------------------------------------------------------
extern "C" void kernel_launch(void* const* d_in, const int* in_sizes, int n_in,
                              void* d_out, int out_size)
{
    const float* desc = (const float*)d_in[0];
    const float* nv   = (const float*)d_in[1];
    // d_in[2]=Wq, d_in[3]=bq dead; d_in[11]=ba dead (cancel in softmax)
    const float* Wk   = (const float*)d_in[4];
    const float* bk   = (const float*)d_in[5];
    const float* Wv   = (const float*)d_in[6];
    const float* bv   = (const float*)d_in[7];
    const float* Wo   = (const float*)d_in[8];
    const float* bo   = (const float*)d_in[9];
    const float* Wa   = (const float*)d_in[10];
    float* out = (float*)d_out;

    cudaFuncSetAttribute(mega_gemm, cudaFuncAttributeMaxDynamicSharedMemorySize, 2 * STG);

    __nv_bfloat16 *pnvh, *pnvl, *pAh, *pAl, *pWvh, *pWvl, *pWoh, *pWol;
    cudaGetSymbolAddress((void**)&pnvh, g_nvh);
    cudaGetSymbolAddress((void**)&pnvl, g_nvl);
    cudaGetSymbolAddress((void**)&pAh, g_Ah);
    cudaGetSymbolAddress((void**)&pAl, g_Al);
    cudaGetSymbolAddress((void**)&pWvh, g_Wvh);
    cudaGetSymbolAddress((void**)&pWvl, g_Wvl);
    cudaGetSymbolAddress((void**)&pWoh, g_Woh);
    cudaGetSymbolAddress((void**)&pWol, g_Wol);
    unsigned* pflag;
    cudaGetSymbolAddress((void**)&pflag, g_flag);

    cudaMemsetAsync(pflag, 0, NB * sizeof(unsigned), 0);
    cvtw_kernel<<<dim3(ND * ND / 1024, 2), 256>>>(Wv, Wo);
    prep_kernel<<<NH, 256>>>(Wk, bk, Wa);
    score_cvt_kernel<<<dim3(NB, 16), 384>>>(nv, desc, Wa);

    mega_gemm<<<768, 256, 2 * STG>>>(pnvh, pnvl, pWvh, pWvl,
                                     pAh, pAl, pWoh, pWol,
                                     bv, bo, out);
}

// round 7
// speedup vs baseline: 5.0215x; 1.0334x over previous
#include <cuda_runtime.h>
#include <cuda_bf16.h>
#include <cstdint>

#define NB 32
#define NS 128
#define ND 768
#define NH 12
#define HD 64
#define NM (NB*NS)   // 4096

// CTA role ranges (bid order == dependency order; HW dispatches ascending)
#define BID_CVT   12
#define BID_SCORE 76
#define BID_PROD  588
#define BID_CONS  972
#define GRID_TOT  1356

// Scratch
__device__ __nv_bfloat16 g_nvh[NB*NS*ND];
__device__ __nv_bfloat16 g_nvl[NB*NS*ND];
__device__ __nv_bfloat16 g_Ah[NB*NS*ND];
__device__ __nv_bfloat16 g_Al[NB*NS*ND];
__device__ __nv_bfloat16 g_Wvh[ND*ND], g_Wvl[ND*ND];
__device__ __nv_bfloat16 g_Woh[ND*ND], g_Wol[ND*ND];
__device__ float g_U[NH*ND];
__device__ float g_c[NH];
__device__ float g_lg[NB*NH*NS];
// flags: [0]=prep(==12) [1]=Wv(==32) [2]=Wo(==32) [3+b]=score_b(==16) [35+b]=prod_b(==12)
__device__ unsigned g_flags[3 + NB + NB];

// ---------------------------------------------------------------------------
__device__ __forceinline__ uint32_t smem_u32(const void* p) {
    uint32_t a;
    asm("{ .reg .u64 t; cvta.to.shared.u64 t, %1; cvt.u32.u64 %0, t; }"
        : "=r"(a) : "l"(p));
    return a;
}
#define SWZ(o) ((o) ^ (((o) >> 3) & 0x70))

__device__ __forceinline__ void ldm_x4(uint32_t* r, uint32_t addr) {
    asm volatile("ldmatrix.sync.aligned.m8n8.x4.shared.b16 {%0,%1,%2,%3}, [%4];"
                 : "=r"(r[0]), "=r"(r[1]), "=r"(r[2]), "=r"(r[3]) : "r"(addr));
}
__device__ __forceinline__ void mma_bf16(float* d, const uint32_t* a, const uint32_t* b) {
    asm volatile(
        "mma.sync.aligned.m16n8k16.row.col.f32.bf16.bf16.f32 "
        "{%0,%1,%2,%3}, {%4,%5,%6,%7}, {%8,%9}, {%0,%1,%2,%3};"
        : "+f"(d[0]), "+f"(d[1]), "+f"(d[2]), "+f"(d[3])
        : "r"(a[0]), "r"(a[1]), "r"(a[2]), "r"(a[3]), "r"(b[0]), "r"(b[1]));
}
__device__ __forceinline__ void cpa16(uint32_t dst, const void* src) {
    asm volatile("cp.async.cg.shared.global [%0], [%1], 16;"
                 :: "r"(dst), "l"(src) : "memory");
}
__device__ __forceinline__ void cpa_commit() {
    asm volatile("cp.async.commit_group;" ::: "memory");
}
__device__ __forceinline__ void cpa_wait0() {
    asm volatile("cp.async.wait_group 0;" ::: "memory");
}
__device__ __forceinline__ uint32_t pack2bf(float a, float b) {
    __nv_bfloat162 t = __floats2bfloat162_rn(a, b);
    return *(uint32_t*)&t;
}
__device__ __forceinline__ float bf_hi(float x) {
    return __bfloat162float(__float2bfloat16(x));
}
__device__ __forceinline__ unsigned ld_acq(const unsigned* p) {
    unsigned v;
    asm volatile("ld.acquire.gpu.global.u32 %0, [%1];" : "=r"(v) : "l"(p));
    return v;
}
__device__ __forceinline__ void wait_flag(const unsigned* p, unsigned tgt) {
    while (ld_acq(p) < tgt) __nanosleep(64);
}
__device__ __forceinline__ void done_flag(unsigned* p) {
    __threadfence();
    atomicAdd(p, 1u);
}

// ---------------------------------------------------------------------------
// GEMM mainloop: acc = X * W^T (hi/lo bf16 split, 3-pass)
// 128(M)x64(N) tile, BK=64, 256 thr, double-buffered cp.async.
// ---------------------------------------------------------------------------
#define STG 49152
__device__ __forceinline__ void gemm_main(
    const __nv_bfloat16* __restrict__ Xh, const __nv_bfloat16* __restrict__ Xl,
    const __nv_bfloat16* __restrict__ Wh, const __nv_bfloat16* __restrict__ Wl,
    char* sm, int bm, int bn, float acc[2][4][4])
{
    const int tid = threadIdx.x;
    const int lane = tid & 31, w = tid >> 5;
    const uint32_t smb = smem_u32(sm);
    const int wm = w >> 1, wn = w & 1;

    const uint32_t a_row = (uint32_t)(wm * 32 + (lane & 15));
    const uint32_t a_kh  = (uint32_t)((lane >> 4) << 4);
    const uint32_t b_row = (uint32_t)(wn * 32 + (lane & 7) + ((lane >> 4) << 3));
    const uint32_t b_kh  = (uint32_t)(((lane >> 3) & 1) << 4);

#pragma unroll
    for (int mt = 0; mt < 2; mt++)
#pragma unroll
        for (int nt = 0; nt < 4; nt++)
#pragma unroll
            for (int i = 0; i < 4; i++) acc[mt][nt][i] = 0.f;

    auto ISSUE = [&](int c, int s) {
        const uint32_t sb = smb + s * STG;
        const int k0 = c * 64;
#pragma unroll
        for (int it = 0; it < 4; it++) {
            const int L = tid + it * 256;
            const int r = L >> 3, k8 = (L & 7);
            const uint32_t so = SWZ((uint32_t)(r * 128 + k8 * 16));
            const size_t go = (size_t)(bm + r) * ND + k0 + k8 * 8;
            cpa16(sb + so,         Xh + go);
            cpa16(sb + 16384 + so, Xl + go);
        }
#pragma unroll
        for (int it = 0; it < 2; it++) {
            const int L = tid + it * 256;
            const int r = L >> 3, k8 = (L & 7);
            const uint32_t so = SWZ((uint32_t)(r * 128 + k8 * 16));
            const size_t go = (size_t)(bn + r) * ND + k0 + k8 * 8;
            cpa16(sb + 32768 + so, Wh + go);
            cpa16(sb + 40960 + so, Wl + go);
        }
        cpa_commit();
    };

    ISSUE(0, 0);
    for (int c = 0; c < 12; c++) {
        cpa_wait0();
        __syncthreads();
        if (c < 11) ISSUE(c + 1, (c + 1) & 1);
        const uint32_t sb = smb + (c & 1) * STG;

#pragma unroll
        for (int ks = 0; ks < 4; ks++) {
            uint32_t ah[2][4], al[2][4], bh[2][4], bl[2][4];
#pragma unroll
            for (int mt = 0; mt < 2; mt++) {
                const uint32_t byo = (a_row + mt * 16) * 128 + ks * 32 + a_kh;
                ldm_x4(ah[mt], sb + SWZ(byo));
                ldm_x4(al[mt], sb + 16384 + SWZ(byo));
            }
#pragma unroll
            for (int nt2 = 0; nt2 < 2; nt2++) {
                const uint32_t byo = (b_row + nt2 * 16) * 128 + ks * 32 + b_kh;
                ldm_x4(bh[nt2], sb + 32768 + SWZ(byo));
                ldm_x4(bl[nt2], sb + 40960 + SWZ(byo));
            }
#pragma unroll
            for (int mt = 0; mt < 2; mt++)
#pragma unroll
                for (int nt = 0; nt < 4; nt++) {
                    const uint32_t* bhp = &bh[nt >> 1][(nt & 1) * 2];
                    const uint32_t* blp = &bl[nt >> 1][(nt & 1) * 2];
                    mma_bf16(acc[mt][nt], ah[mt], bhp);
                    mma_bf16(acc[mt][nt], ah[mt], blp);
                    mma_bf16(acc[mt][nt], al[mt], bhp);
                }
        }
        __syncthreads();
    }
}

// ---------------------------------------------------------------------------
// ONE kernel, flag-gated phases.
// ---------------------------------------------------------------------------
__global__ __launch_bounds__(256, 2)
void fused_all(const float* __restrict__ desc, const float* __restrict__ nv,
               const float* __restrict__ Wk, const float* __restrict__ bk,
               const float* __restrict__ Wv, const float* __restrict__ bv,
               const float* __restrict__ Wo, const float* __restrict__ bo,
               const float* __restrict__ Wa, float* __restrict__ out)
{
    extern __shared__ __align__(1024) char sm[];
    __shared__ float sp[NS];
    __shared__ float spart[8];
    __shared__ float sred[256];
    __shared__ float svs[HD];
    __shared__ float swk[HD];

    const int bid = blockIdx.x;
    const int tid = threadIdx.x;
    const int lane = tid & 31, w = tid >> 5;
    const int wm = w >> 1, wn = w & 1;

    if (bid < BID_CVT) {
        // ---------------- PREP: g_U[h], g_c[h] ----------------
        const int h = bid;
        if (tid < HD) swk[tid] = Wa[HD + tid];
        __syncthreads();
        for (int k = tid; k < ND; k += 256) {
            float a = 0.f;
#pragma unroll 8
            for (int d = 0; d < HD; d++)
                a += swk[d] * Wk[(size_t)(h * HD + d) * ND + k];
            g_U[h * ND + k] = a;
        }
        if (tid == 0) {
            float cc = 0.f;
            for (int d = 0; d < HD; d++) cc += swk[d] * bk[h * HD + d];
            g_c[h] = cc;
        }
        __syncthreads();
        if (tid == 0) done_flag(&g_flags[0]);

    } else if (bid < BID_SCORE) {
        // ---------------- CVT weights to hi/lo ----------------
        const int cid = bid - BID_CVT;
        const int half = cid >> 5;            // 0=Wv 1=Wo
        const int seg = cid & 31;
        const float* src = half ? Wo : Wv;
        uint32_t* hi = (uint32_t*)(half ? g_Woh : g_Wvh);
        uint32_t* lo = (uint32_t*)(half ? g_Wol : g_Wvl);
        const int base = seg * 4608;          // f4 units; 147456/32
#pragma unroll 2
        for (int it = 0; it < 18; it++) {
            const int lin = base + it * 256 + tid;
            float4 v = *(const float4*)(src + (size_t)lin * 4);
            float h0 = bf_hi(v.x), h1 = bf_hi(v.y), h2 = bf_hi(v.z), h3 = bf_hi(v.w);
            *(uint2*)(hi + (size_t)lin * 2) =
                make_uint2(pack2bf(v.x, v.y), pack2bf(v.z, v.w));
            *(uint2*)(lo + (size_t)lin * 2) =
                make_uint2(pack2bf(v.x - h0, v.y - h1), pack2bf(v.z - h2, v.w - h3));
        }
        __syncthreads();
        if (tid == 0) done_flag(&g_flags[1 + half]);

    } else if (bid < BID_PROD) {
        // ---------------- SCORE + nv split (8 rows) ----------------
        const int sid = bid - BID_SCORE;
        const int b = sid >> 4;
        const int j0 = (sid & 15) * 8;
        float* s_nv = (float*)sm;                    // 8x768
        float* s_ds = (float*)(sm + 24576);          // 8x768

        if (tid == 0) wait_flag(&g_flags[0], 12u);
        __syncthreads();

        const size_t gbase = ((size_t)b * NS + j0) * ND;
        const float* src = nv + gbase;
        uint32_t* nvh = (uint32_t*)g_nvh;
        uint32_t* nvl = (uint32_t*)g_nvl;
#pragma unroll
        for (int it = 0; it < 6; it++) {
            const int lin = tid + it * 256;          // 0..1535 f4
            float4 v = *(const float4*)(src + lin * 4);
            *(float4*)(s_nv + lin * 4) = v;
            float h0 = bf_hi(v.x), h1 = bf_hi(v.y), h2 = bf_hi(v.z), h3 = bf_hi(v.w);
            size_t ui = gbase / 2 + (size_t)lin * 2;
            *(uint2*)(nvh + ui) = make_uint2(pack2bf(v.x, v.y), pack2bf(v.z, v.w));
            *(uint2*)(nvl + ui) =
                make_uint2(pack2bf(v.x - h0, v.y - h1), pack2bf(v.z - h2, v.w - h3));
            const int r = lin / 192, c4 = lin % 192;
            const int drow = j0 + r - 1;
            float4 dv = (drow >= 0)
                ? *(const float4*)(desc + ((size_t)b * (NS - 1) + drow) * ND + c4 * 4)
                : make_float4(0.f, 0.f, 0.f, 0.f);
            *(float4*)(s_ds + r * ND + c4 * 4) = dv;
        }
        __syncthreads();

        const float we0 = Wa[2 * HD + lane], we1 = Wa[2 * HD + 32 + lane];
        for (int h = w; h < NH; h += 8) {
            float u[24];
#pragma unroll
            for (int t = 0; t < 24; t++) u[t] = g_U[h * ND + t * 32 + lane];
            const float ch = g_c[h];
#pragma unroll
            for (int j = 0; j < 8; j++) {
                float acc = 0.f;
#pragma unroll
                for (int t = 0; t < 24; t++) acc += s_nv[j * ND + t * 32 + lane] * u[t];
                acc += s_ds[j * ND + h * 64 + lane] * we0
                     + s_ds[j * ND + h * 64 + 32 + lane] * we1;
#pragma unroll
                for (int off = 16; off > 0; off >>= 1)
                    acc += __shfl_xor_sync(0xFFFFFFFF, acc, off);
                if (lane == 0)
                    g_lg[((size_t)b * NH + h) * NS + j0 + j] =
                        (j0 + j >= 1) ? acc + ch : 0.f;
            }
        }
        __syncthreads();
        if (tid == 0) done_flag(&g_flags[3 + b]);

    } else if (bid < BID_CONS) {
        // ---------------- PRODUCER: V proj + softmax + attention ------------
        const int pid = bid - BID_PROD;
        const int h = pid % NH, b = pid / NH;
        const int bm = b * 128, bn = h * 64;

        if (tid == 0) {
            wait_flag(&g_flags[3 + b], 16u);
            wait_flag(&g_flags[1], 32u);
        }
        __syncthreads();

        // softmax row (b,h)
        const float* lg = g_lg + ((size_t)b * NH + h) * NS;
        float l = -1e30f;
        if (tid >= 1 && tid < NS) l = lg[tid];
        float wmx = l;
#pragma unroll
        for (int off = 16; off > 0; off >>= 1)
            wmx = fmaxf(wmx, __shfl_xor_sync(0xFFFFFFFF, wmx, off));
        if (lane == 0 && w < 4) spart[w] = wmx;
        __syncthreads();
        const float m = fmaxf(fmaxf(spart[0], spart[1]), fmaxf(spart[2], spart[3]));
        const float pe = (tid >= 1 && tid < NS) ? expf(l - m) : 0.f;
        if (tid < NS) sp[tid] = pe;
        float ws = pe;
#pragma unroll
        for (int off = 16; off > 0; off >>= 1)
            ws += __shfl_xor_sync(0xFFFFFFFF, ws, off);
        if (lane == 0 && w < 4) spart[4 + w] = ws;
        __syncthreads();

        float acc[2][4][4];
        gemm_main(g_nvh, g_nvl, g_Wvh, g_Wvl, sm, bm, bn, acc);

        float* sVt = (float*)sm;
        const int r_base = wm * 32 + (lane >> 2);
        const int c_base = wn * 32 + ((lane & 3) << 1);
#pragma unroll
        for (int mt = 0; mt < 2; mt++)
#pragma unroll
            for (int nt = 0; nt < 4; nt++) {
                const int c = c_base + nt * 8;
                const float b0 = bv[bn + c], b1 = bv[bn + c + 1];
                const int r0 = r_base + mt * 16;
                *(float2*)&sVt[r0 * 64 + c] =
                    make_float2(acc[mt][nt][0] + b0, acc[mt][nt][1] + b1);
                *(float2*)&sVt[(r0 + 8) * 64 + c] =
                    make_float2(acc[mt][nt][2] + b0, acc[mt][nt][3] + b1);
            }
        __syncthreads();

        const float S = spart[4] + spart[5] + spart[6] + spart[7];
        const int d = tid & 63;
        const int q = tid >> 6;
        float av = 0.f;
#pragma unroll 4
        for (int j = q; j < NS; j += 4) av += sp[j] * sVt[j * 64 + d];
        sred[tid] = av;
        __syncthreads();
        if (tid < HD)
            svs[tid] = sred[tid] + sred[tid + 64] + sred[tid + 128] + sred[tid + 192];
        __syncthreads();

        const float vs = svs[d];
        __nv_bfloat16* pAh = g_Ah + ((size_t)b * NS) * ND + bn + d;
        __nv_bfloat16* pAl = g_Al + ((size_t)b * NS) * ND + bn + d;
#pragma unroll 4
        for (int i = q; i < NS; i += 4) {
            const float pi = sp[i];
            const float val = __fdividef(vs - pi * sVt[i * 64 + d], S - pi);
            const float hi = bf_hi(val);
            pAh[(size_t)i * ND] = __float2bfloat16(val);
            pAl[(size_t)i * ND] = __float2bfloat16(val - hi);
        }
        __syncthreads();
        if (tid == 0) done_flag(&g_flags[35 + b]);

    } else {
        // ---------------- CONSUMER: out projection ----------------
        const int cid = bid - BID_CONS;
        const int bn = (cid % 12) * 64;
        const int b  = cid / 12;
        const int bm = b * 128;

        if (tid == 0) {
            wait_flag(&g_flags[35 + b], 12u);
            wait_flag(&g_flags[2], 32u);
        }
        __syncthreads();

        float acc[2][4][4];
        gemm_main(g_Ah, g_Al, g_Woh, g_Wol, sm, bm, bn, acc);

        const int erow = bm + wm * 32 + (lane >> 2);
        const int ecol0 = bn + wn * 32 + ((lane & 3) << 1);
#pragma unroll
        for (int mt = 0; mt < 2; mt++)
#pragma unroll
            for (int nt = 0; nt < 4; nt++) {
                const int col = ecol0 + nt * 8;
                const float b0 = bo[col], b1 = bo[col + 1];
                const int r0 = erow + mt * 16;
                *(float2*)(out + (size_t)r0 * ND + col) =
                    make_float2(acc[mt][nt][0] + b0, acc[mt][nt][1] + b1);
                *(float2*)(out + (size_t)(r0 + 8) * ND + col) =
                    make_float2(acc[mt][nt][2] + b0, acc[mt][nt][3] + b1);
            }
    }
}

// ---------------------------------------------------------------------------
extern "C" void kernel_launch(void* const* d_in, const int* in_sizes, int n_in,
                              void* d_out, int out_size)
{
    const float* desc = (const float*)d_in[0];
    const float* nv   = (const float*)d_in[1];
    // d_in[2]=Wq, d_in[3]=bq dead; d_in[11]=ba dead (cancel in softmax)
    const float* Wk   = (const float*)d_in[4];
    const float* bk   = (const float*)d_in[5];
    const float* Wv   = (const float*)d_in[6];
    const float* bv   = (const float*)d_in[7];
    const float* Wo   = (const float*)d_in[8];
    const float* bo   = (const float*)d_in[9];
    const float* Wa   = (const float*)d_in[10];
    float* out = (float*)d_out;

    cudaFuncSetAttribute(fused_all, cudaFuncAttributeMaxDynamicSharedMemorySize, 2 * STG);

    unsigned* pflag;
    cudaGetSymbolAddress((void**)&pflag, g_flags);
    cudaMemsetAsync(pflag, 0, (3 + NB + NB) * sizeof(unsigned), 0);

    fused_all<<<GRID_TOT, 256, 2 * STG>>>(desc, nv, Wk, bk, Wv, bv, Wo, bo, Wa, out);
}